// round 1
// baseline (speedup 1.0000x reference)
#include <cuda_runtime.h>

// ---------------------------------------------------------------------------
// CrossAttention: out = softmax((xWq)(ctxWk)^T / sqrt(64)) (ctxWv) Wo + bo
// B=4, N=M=2048, QUERY_DIM=INNER=512, H=8, D=64
// Round 1: fp32 exact pipeline with packed fma.rn.f32x2 (FFMA2) microkernels.
// ---------------------------------------------------------------------------

#define BB    4
#define SEQ   2048
#define HH    8
#define DH    64
#define CD    512
#define ROWS  (BB*SEQ)          // 8192

// Scratch (allocation-free rule: __device__ globals)
__device__ float g_Q[BB*HH*SEQ*DH];   // [b][h][n][d]
__device__ float g_K[BB*HH*SEQ*DH];
__device__ float g_V[BB*HH*SEQ*DH];
__device__ float g_Oc[BB*SEQ*CD];     // [b][n][h*64+d]  (pre-Wo)

// ---- packed f32x2 helpers --------------------------------------------------
__device__ __forceinline__ unsigned long long pk2(float x, float y) {
    unsigned long long r;
    asm("mov.b64 %0, {%1, %2};" : "=l"(r) : "f"(x), "f"(y));
    return r;
}
__device__ __forceinline__ void upk2(unsigned long long v, float& x, float& y) {
    asm("mov.b64 {%0, %1}, %2;" : "=f"(x), "=f"(y) : "l"(v));
}
__device__ __forceinline__ void ffma2(unsigned long long& d,
                                      unsigned long long a, unsigned long long b) {
    asm("fma.rn.f32x2 %0, %1, %2, %0;" : "+l"(d) : "l"(a), "l"(b));
}
__device__ __forceinline__ void fmul2(unsigned long long& d, unsigned long long a) {
    asm("mul.rn.f32x2 %0, %1, %0;" : "+l"(d) : "l"(a));
}

// ---------------------------------------------------------------------------
// Projection GEMM: C[8192x512] = A[8192x512] * W[512x512]
// 128x128 block tile, BK=8, 256 threads, 8x8 per thread (split 4+4 tiles).
// z=0: Q = x@Wq ; z=1: K = ctx@Wk ; z=2: V = ctx@Wv. Output head-split layout.
// ---------------------------------------------------------------------------
__global__ __launch_bounds__(256) void proj_gemm(
    const float* __restrict__ x, const float* __restrict__ ctx,
    const float* __restrict__ Wq, const float* __restrict__ Wk,
    const float* __restrict__ Wv)
{
    const float* A; const float* W; float* Out;
    if (blockIdx.z == 0)      { A = x;   W = Wq; Out = g_Q; }
    else if (blockIdx.z == 1) { A = ctx; W = Wk; Out = g_K; }
    else                      { A = ctx; W = Wv; Out = g_V; }

    __shared__ float As[8][128];
    __shared__ float Ws[8][128];

    const int tid = threadIdx.x;
    const int tx  = tid & 15;
    const int ty  = tid >> 4;
    const int row0 = blockIdx.y * 128;
    const int col0 = blockIdx.x * 128;

    const int arow = tid >> 1;          // 0..127
    const int acol = (tid & 1) * 4;     // 0 or 4
    const int wrow = tid >> 5;          // 0..7
    const int wcol = (tid & 31) * 4;    // 0..124

    unsigned long long c2[8][4];
    #pragma unroll
    for (int i = 0; i < 8; i++)
        #pragma unroll
        for (int j = 0; j < 4; j++) c2[i][j] = 0ull;   // (0.0f, 0.0f)

    for (int k0 = 0; k0 < CD; k0 += 8) {
        float4 av = *(const float4*)(A + (size_t)(row0 + arow) * CD + k0 + acol);
        float4 wv = *(const float4*)(W + (size_t)(k0 + wrow) * CD + col0 + wcol);
        __syncthreads();
        As[acol + 0][arow] = av.x;
        As[acol + 1][arow] = av.y;
        As[acol + 2][arow] = av.z;
        As[acol + 3][arow] = av.w;
        *(float4*)&Ws[wrow][wcol] = wv;
        __syncthreads();

        #pragma unroll
        for (int kk = 0; kk < 8; kk++) {
            float4 a0 = *(const float4*)&As[kk][ty * 4];
            float4 a1 = *(const float4*)&As[kk][64 + ty * 4];
            ulonglong2 b0 = *(const ulonglong2*)&Ws[kk][tx * 4];
            ulonglong2 b1 = *(const ulonglong2*)&Ws[kk][64 + tx * 4];
            float a[8] = {a0.x, a0.y, a0.z, a0.w, a1.x, a1.y, a1.z, a1.w};
            unsigned long long bp[4] = {b0.x, b0.y, b1.x, b1.y};
            #pragma unroll
            for (int i = 0; i < 8; i++) {
                unsigned long long ad = pk2(a[i], a[i]);
                #pragma unroll
                for (int j = 0; j < 4; j++) ffma2(c2[i][j], ad, bp[j]);
            }
        }
    }

    // epilogue: write into [b][h][n][d] head-split layout
    #pragma unroll
    for (int i = 0; i < 8; i++) {
        int R = row0 + ((i < 4) ? (ty * 4 + i) : (64 + ty * 4 + (i - 4)));
        int b = R >> 11;            // /2048
        int n = R & 2047;
        float c[8];
        #pragma unroll
        for (int j = 0; j < 4; j++) upk2(c2[i][j], c[2 * j], c[2 * j + 1]);
        #pragma unroll
        for (int j = 0; j < 8; j++) {
            int col = col0 + ((j < 4) ? (tx * 4 + j) : (64 + tx * 4 + (j - 4)));
            int h = col >> 6;
            int d = col & 63;
            Out[(((size_t)(b * HH + h)) * SEQ + n) * DH + d] = c[j];
        }
    }
}

// ---------------------------------------------------------------------------
// Flash attention, fp32, online softmax.
// Block: 256 threads, 64-query tile; loop over 64-key chunks.
// Thread (tx,ty): rows ty*4..+3, dims/cols tx*4..+3.
// ---------------------------------------------------------------------------
#define PAD 68
#define ATTN_SMEM (4 * 64 * PAD * 4)

__global__ __launch_bounds__(256) void attn_kernel()
{
    extern __shared__ float sm[];
    float* Qs = sm;
    float* Ks = sm + 64 * PAD;
    float* Vs = sm + 2 * 64 * PAD;
    float* Ps = sm + 3 * 64 * PAD;

    const int tid = threadIdx.x;
    const int tx  = tid & 15;
    const int ty  = tid >> 4;
    const int q0  = blockIdx.x * 64;
    const int h   = blockIdx.y;
    const int b   = blockIdx.z;

    const float* Qg = g_Q + (((size_t)(b * HH + h)) * SEQ + q0) * DH;
    const float* Kg = g_K + ((size_t)(b * HH + h)) * SEQ * DH;
    const float* Vg = g_V + ((size_t)(b * HH + h)) * SEQ * DH;

    const float scale = 0.125f;   // 1/sqrt(64)

    // load Q tile (scaled)
    #pragma unroll
    for (int i = 0; i < 4; i++) {
        int lin = i * 256 + tid;            // float4 index, 1024 total
        int r = lin >> 4;
        int c4 = (lin & 15) << 2;
        float4 v = *(const float4*)(Qg + r * DH + c4);
        v.x *= scale; v.y *= scale; v.z *= scale; v.w *= scale;
        *(float4*)&Qs[r * PAD + c4] = v;
    }

    float m_i[4], l_i[4];
    unsigned long long o2[4][2];
    #pragma unroll
    for (int i = 0; i < 4; i++) {
        m_i[i] = -1e30f; l_i[i] = 0.0f;
        o2[i][0] = 0ull; o2[i][1] = 0ull;
    }

    for (int m0 = 0; m0 < SEQ; m0 += 64) {
        __syncthreads();   // protect prior-iteration readers of Ks/Vs/Ps (and Qs writes on iter 0)
        #pragma unroll
        for (int i = 0; i < 4; i++) {
            int lin = i * 256 + tid;
            int r = lin >> 4;
            int c4 = (lin & 15) << 2;
            *(float4*)&Ks[r * PAD + c4] = *(const float4*)(Kg + (size_t)(m0 + r) * DH + c4);
            *(float4*)&Vs[r * PAD + c4] = *(const float4*)(Vg + (size_t)(m0 + r) * DH + c4);
        }
        __syncthreads();

        // S = Q K^T (paired over d)
        unsigned long long s2[4][4];
        #pragma unroll
        for (int i = 0; i < 4; i++)
            #pragma unroll
            for (int j = 0; j < 4; j++) s2[i][j] = 0ull;

        #pragma unroll
        for (int d0 = 0; d0 < DH; d0 += 4) {
            ulonglong2 qp[4], kp[4];
            #pragma unroll
            for (int i = 0; i < 4; i++)
                qp[i] = *(const ulonglong2*)&Qs[(ty * 4 + i) * PAD + d0];
            #pragma unroll
            for (int j = 0; j < 4; j++)
                kp[j] = *(const ulonglong2*)&Ks[(tx * 4 + j) * PAD + d0];
            #pragma unroll
            for (int i = 0; i < 4; i++)
                #pragma unroll
                for (int j = 0; j < 4; j++) {
                    ffma2(s2[i][j], qp[i].x, kp[j].x);
                    ffma2(s2[i][j], qp[i].y, kp[j].y);
                }
        }

        float s[4][4];
        #pragma unroll
        for (int i = 0; i < 4; i++)
            #pragma unroll
            for (int j = 0; j < 4; j++) {
                float lo, hi;
                upk2(s2[i][j], lo, hi);
                s[i][j] = lo + hi;
            }

        // online softmax (row stats replicated across the 16 tx threads)
        #pragma unroll
        for (int i = 0; i < 4; i++) {
            float cm = fmaxf(fmaxf(s[i][0], s[i][1]), fmaxf(s[i][2], s[i][3]));
            #pragma unroll
            for (int o = 8; o >= 1; o >>= 1)
                cm = fmaxf(cm, __shfl_xor_sync(0xffffffffu, cm, o));
            float mn = fmaxf(m_i[i], cm);
            float alpha = __expf(m_i[i] - mn);
            float p0 = __expf(s[i][0] - mn);
            float p1 = __expf(s[i][1] - mn);
            float p2 = __expf(s[i][2] - mn);
            float p3 = __expf(s[i][3] - mn);
            float rs = (p0 + p1) + (p2 + p3);
            #pragma unroll
            for (int o = 8; o >= 1; o >>= 1)
                rs += __shfl_xor_sync(0xffffffffu, rs, o);
            l_i[i] = l_i[i] * alpha + rs;
            m_i[i] = mn;
            unsigned long long ap = pk2(alpha, alpha);
            fmul2(o2[i][0], ap);
            fmul2(o2[i][1], ap);
            *(float4*)&Ps[(ty * 4 + i) * PAD + tx * 4] = make_float4(p0, p1, p2, p3);
        }
        __syncthreads();

        // O += P V (paired over output cols)
        #pragma unroll
        for (int c0 = 0; c0 < 64; c0 += 4) {
            float4 pv[4];
            #pragma unroll
            for (int i = 0; i < 4; i++)
                pv[i] = *(const float4*)&Ps[(ty * 4 + i) * PAD + c0];
            #pragma unroll
            for (int cc = 0; cc < 4; cc++) {
                ulonglong2 vv = *(const ulonglong2*)&Vs[(c0 + cc) * PAD + tx * 4];
                float pr[4] = {pv[0].x, pv[1].x, pv[2].x, pv[3].x};
                // select the cc-th component of each pv
                if (cc == 1) { pr[0] = pv[0].y; pr[1] = pv[1].y; pr[2] = pv[2].y; pr[3] = pv[3].y; }
                if (cc == 2) { pr[0] = pv[0].z; pr[1] = pv[1].z; pr[2] = pv[2].z; pr[3] = pv[3].z; }
                if (cc == 3) { pr[0] = pv[0].w; pr[1] = pv[1].w; pr[2] = pv[2].w; pr[3] = pv[3].w; }
                #pragma unroll
                for (int i = 0; i < 4; i++) {
                    unsigned long long pd = pk2(pr[i], pr[i]);
                    ffma2(o2[i][0], pd, vv.x);
                    ffma2(o2[i][1], pd, vv.y);
                }
            }
        }
    }

    // finalize: O / l, write to [b][n][h*64+d]
    #pragma unroll
    for (int i = 0; i < 4; i++) {
        float inv = 1.0f / l_i[i];
        float o0, o1, o2v, o3;
        upk2(o2[i][0], o0, o1);
        upk2(o2[i][1], o2v, o3);
        int n = q0 + ty * 4 + i;
        float4 outv = make_float4(o0 * inv, o1 * inv, o2v * inv, o3 * inv);
        *(float4*)(g_Oc + ((size_t)(b * SEQ + n)) * CD + h * DH + tx * 4) = outv;
    }
}

// ---------------------------------------------------------------------------
// Output GEMM: out[8192x512] = g_Oc @ Wo + bo
// ---------------------------------------------------------------------------
__global__ __launch_bounds__(256) void out_gemm(
    const float* __restrict__ Wo, const float* __restrict__ bo,
    float* __restrict__ out)
{
    __shared__ float As[8][128];
    __shared__ float Ws[8][128];

    const int tid = threadIdx.x;
    const int tx  = tid & 15;
    const int ty  = tid >> 4;
    const int row0 = blockIdx.y * 128;
    const int col0 = blockIdx.x * 128;

    const int arow = tid >> 1;
    const int acol = (tid & 1) * 4;
    const int wrow = tid >> 5;
    const int wcol = (tid & 31) * 4;

    unsigned long long c2[8][4];
    #pragma unroll
    for (int i = 0; i < 8; i++)
        #pragma unroll
        for (int j = 0; j < 4; j++) c2[i][j] = 0ull;

    for (int k0 = 0; k0 < CD; k0 += 8) {
        float4 av = *(const float4*)(g_Oc + (size_t)(row0 + arow) * CD + k0 + acol);
        float4 wv = *(const float4*)(Wo + (size_t)(k0 + wrow) * CD + col0 + wcol);
        __syncthreads();
        As[acol + 0][arow] = av.x;
        As[acol + 1][arow] = av.y;
        As[acol + 2][arow] = av.z;
        As[acol + 3][arow] = av.w;
        *(float4*)&Ws[wrow][wcol] = wv;
        __syncthreads();

        #pragma unroll
        for (int kk = 0; kk < 8; kk++) {
            float4 a0 = *(const float4*)&As[kk][ty * 4];
            float4 a1 = *(const float4*)&As[kk][64 + ty * 4];
            ulonglong2 b0 = *(const ulonglong2*)&Ws[kk][tx * 4];
            ulonglong2 b1 = *(const ulonglong2*)&Ws[kk][64 + tx * 4];
            float a[8] = {a0.x, a0.y, a0.z, a0.w, a1.x, a1.y, a1.z, a1.w};
            unsigned long long bp[4] = {b0.x, b0.y, b1.x, b1.y};
            #pragma unroll
            for (int i = 0; i < 8; i++) {
                unsigned long long ad = pk2(a[i], a[i]);
                #pragma unroll
                for (int j = 0; j < 4; j++) ffma2(c2[i][j], ad, bp[j]);
            }
        }
    }

    #pragma unroll
    for (int i = 0; i < 8; i++) {
        int R = row0 + ((i < 4) ? (ty * 4 + i) : (64 + ty * 4 + (i - 4)));
        float c[8];
        #pragma unroll
        for (int j = 0; j < 4; j++) upk2(c2[i][j], c[2 * j], c[2 * j + 1]);
        #pragma unroll
        for (int j = 0; j < 8; j++) {
            int col = col0 + ((j < 4) ? (tx * 4 + j) : (64 + tx * 4 + (j - 4)));
            out[(size_t)R * CD + col] = c[j] + bo[col];
        }
    }
}

// ---------------------------------------------------------------------------
extern "C" void kernel_launch(void* const* d_in, const int* in_sizes, int n_in,
                              void* d_out, int out_size)
{
    const float* x   = (const float*)d_in[0];
    const float* ctx = (const float*)d_in[1];
    const float* Wq  = (const float*)d_in[2];
    const float* Wk  = (const float*)d_in[3];
    const float* Wv  = (const float*)d_in[4];
    const float* Wo  = (const float*)d_in[5];
    const float* bo  = (const float*)d_in[6];
    float* out = (float*)d_out;

    cudaFuncSetAttribute(attn_kernel,
                         cudaFuncAttributeMaxDynamicSharedMemorySize, ATTN_SMEM);

    proj_gemm<<<dim3(4, 64, 3), 256>>>(x, ctx, Wq, Wk, Wv);
    attn_kernel<<<dim3(SEQ / 64, HH, BB), 256, ATTN_SMEM>>>();
    out_gemm<<<dim3(4, 64), 256>>>(Wo, bo, out);
}

// round 2
// speedup vs baseline: 1.0009x; 1.0009x over previous
#include <cuda_runtime.h>

// ---------------------------------------------------------------------------
// CrossAttention: out = softmax((xWq)(ctxWk)^T / sqrt(64)) (ctxWv) Wo + bo
// B=4, N=M=2048, QUERY_DIM=INNER=512, H=8, D=64
// Round 1: fp32 exact pipeline with packed fma.rn.f32x2 (FFMA2) microkernels.
// ---------------------------------------------------------------------------

#define BB    4
#define SEQ   2048
#define HH    8
#define DH    64
#define CD    512
#define ROWS  (BB*SEQ)          // 8192

// Scratch (allocation-free rule: __device__ globals)
__device__ float g_Q[BB*HH*SEQ*DH];   // [b][h][n][d]
__device__ float g_K[BB*HH*SEQ*DH];
__device__ float g_V[BB*HH*SEQ*DH];
__device__ float g_Oc[BB*SEQ*CD];     // [b][n][h*64+d]  (pre-Wo)

// ---- packed f32x2 helpers --------------------------------------------------
__device__ __forceinline__ unsigned long long pk2(float x, float y) {
    unsigned long long r;
    asm("mov.b64 %0, {%1, %2};" : "=l"(r) : "f"(x), "f"(y));
    return r;
}
__device__ __forceinline__ void upk2(unsigned long long v, float& x, float& y) {
    asm("mov.b64 {%0, %1}, %2;" : "=f"(x), "=f"(y) : "l"(v));
}
__device__ __forceinline__ void ffma2(unsigned long long& d,
                                      unsigned long long a, unsigned long long b) {
    asm("fma.rn.f32x2 %0, %1, %2, %0;" : "+l"(d) : "l"(a), "l"(b));
}
__device__ __forceinline__ void fmul2(unsigned long long& d, unsigned long long a) {
    asm("mul.rn.f32x2 %0, %1, %0;" : "+l"(d) : "l"(a));
}

// ---------------------------------------------------------------------------
// Projection GEMM: C[8192x512] = A[8192x512] * W[512x512]
// 128x128 block tile, BK=8, 256 threads, 8x8 per thread (split 4+4 tiles).
// z=0: Q = x@Wq ; z=1: K = ctx@Wk ; z=2: V = ctx@Wv. Output head-split layout.
// ---------------------------------------------------------------------------
__global__ __launch_bounds__(256) void proj_gemm(
    const float* __restrict__ x, const float* __restrict__ ctx,
    const float* __restrict__ Wq, const float* __restrict__ Wk,
    const float* __restrict__ Wv)
{
    const float* A; const float* W; float* Out;
    if (blockIdx.z == 0)      { A = x;   W = Wq; Out = g_Q; }
    else if (blockIdx.z == 1) { A = ctx; W = Wk; Out = g_K; }
    else                      { A = ctx; W = Wv; Out = g_V; }

    __shared__ float As[8][128];
    __shared__ float Ws[8][128];

    const int tid = threadIdx.x;
    const int tx  = tid & 15;
    const int ty  = tid >> 4;
    const int row0 = blockIdx.y * 128;
    const int col0 = blockIdx.x * 128;

    const int arow = tid >> 1;          // 0..127
    const int acol = (tid & 1) * 4;     // 0 or 4
    const int wrow = tid >> 5;          // 0..7
    const int wcol = (tid & 31) * 4;    // 0..124

    unsigned long long c2[8][4];
    #pragma unroll
    for (int i = 0; i < 8; i++)
        #pragma unroll
        for (int j = 0; j < 4; j++) c2[i][j] = 0ull;   // (0.0f, 0.0f)

    for (int k0 = 0; k0 < CD; k0 += 8) {
        float4 av = *(const float4*)(A + (size_t)(row0 + arow) * CD + k0 + acol);
        float4 wv = *(const float4*)(W + (size_t)(k0 + wrow) * CD + col0 + wcol);
        __syncthreads();
        As[acol + 0][arow] = av.x;
        As[acol + 1][arow] = av.y;
        As[acol + 2][arow] = av.z;
        As[acol + 3][arow] = av.w;
        *(float4*)&Ws[wrow][wcol] = wv;
        __syncthreads();

        #pragma unroll
        for (int kk = 0; kk < 8; kk++) {
            float4 a0 = *(const float4*)&As[kk][ty * 4];
            float4 a1 = *(const float4*)&As[kk][64 + ty * 4];
            ulonglong2 b0 = *(const ulonglong2*)&Ws[kk][tx * 4];
            ulonglong2 b1 = *(const ulonglong2*)&Ws[kk][64 + tx * 4];
            float a[8] = {a0.x, a0.y, a0.z, a0.w, a1.x, a1.y, a1.z, a1.w};
            unsigned long long bp[4] = {b0.x, b0.y, b1.x, b1.y};
            #pragma unroll
            for (int i = 0; i < 8; i++) {
                unsigned long long ad = pk2(a[i], a[i]);
                #pragma unroll
                for (int j = 0; j < 4; j++) ffma2(c2[i][j], ad, bp[j]);
            }
        }
    }

    // epilogue: write into [b][h][n][d] head-split layout
    #pragma unroll
    for (int i = 0; i < 8; i++) {
        int R = row0 + ((i < 4) ? (ty * 4 + i) : (64 + ty * 4 + (i - 4)));
        int b = R >> 11;            // /2048
        int n = R & 2047;
        float c[8];
        #pragma unroll
        for (int j = 0; j < 4; j++) upk2(c2[i][j], c[2 * j], c[2 * j + 1]);
        #pragma unroll
        for (int j = 0; j < 8; j++) {
            int col = col0 + ((j < 4) ? (tx * 4 + j) : (64 + tx * 4 + (j - 4)));
            int h = col >> 6;
            int d = col & 63;
            Out[(((size_t)(b * HH + h)) * SEQ + n) * DH + d] = c[j];
        }
    }
}

// ---------------------------------------------------------------------------
// Flash attention, fp32, online softmax.
// Block: 256 threads, 64-query tile; loop over 64-key chunks.
// Thread (tx,ty): rows ty*4..+3, dims/cols tx*4..+3.
// ---------------------------------------------------------------------------
#define PAD 68
#define ATTN_SMEM (4 * 64 * PAD * 4)

__global__ __launch_bounds__(256) void attn_kernel()
{
    extern __shared__ float sm[];
    float* Qs = sm;
    float* Ks = sm + 64 * PAD;
    float* Vs = sm + 2 * 64 * PAD;
    float* Ps = sm + 3 * 64 * PAD;

    const int tid = threadIdx.x;
    const int tx  = tid & 15;
    const int ty  = tid >> 4;
    const int q0  = blockIdx.x * 64;
    const int h   = blockIdx.y;
    const int b   = blockIdx.z;

    const float* Qg = g_Q + (((size_t)(b * HH + h)) * SEQ + q0) * DH;
    const float* Kg = g_K + ((size_t)(b * HH + h)) * SEQ * DH;
    const float* Vg = g_V + ((size_t)(b * HH + h)) * SEQ * DH;

    const float scale = 0.125f;   // 1/sqrt(64)

    // load Q tile (scaled)
    #pragma unroll
    for (int i = 0; i < 4; i++) {
        int lin = i * 256 + tid;            // float4 index, 1024 total
        int r = lin >> 4;
        int c4 = (lin & 15) << 2;
        float4 v = *(const float4*)(Qg + r * DH + c4);
        v.x *= scale; v.y *= scale; v.z *= scale; v.w *= scale;
        *(float4*)&Qs[r * PAD + c4] = v;
    }

    float m_i[4], l_i[4];
    unsigned long long o2[4][2];
    #pragma unroll
    for (int i = 0; i < 4; i++) {
        m_i[i] = -1e30f; l_i[i] = 0.0f;
        o2[i][0] = 0ull; o2[i][1] = 0ull;
    }

    for (int m0 = 0; m0 < SEQ; m0 += 64) {
        __syncthreads();   // protect prior-iteration readers of Ks/Vs/Ps (and Qs writes on iter 0)
        #pragma unroll
        for (int i = 0; i < 4; i++) {
            int lin = i * 256 + tid;
            int r = lin >> 4;
            int c4 = (lin & 15) << 2;
            *(float4*)&Ks[r * PAD + c4] = *(const float4*)(Kg + (size_t)(m0 + r) * DH + c4);
            *(float4*)&Vs[r * PAD + c4] = *(const float4*)(Vg + (size_t)(m0 + r) * DH + c4);
        }
        __syncthreads();

        // S = Q K^T (paired over d)
        unsigned long long s2[4][4];
        #pragma unroll
        for (int i = 0; i < 4; i++)
            #pragma unroll
            for (int j = 0; j < 4; j++) s2[i][j] = 0ull;

        #pragma unroll
        for (int d0 = 0; d0 < DH; d0 += 4) {
            ulonglong2 qp[4], kp[4];
            #pragma unroll
            for (int i = 0; i < 4; i++)
                qp[i] = *(const ulonglong2*)&Qs[(ty * 4 + i) * PAD + d0];
            #pragma unroll
            for (int j = 0; j < 4; j++)
                kp[j] = *(const ulonglong2*)&Ks[(tx * 4 + j) * PAD + d0];
            #pragma unroll
            for (int i = 0; i < 4; i++)
                #pragma unroll
                for (int j = 0; j < 4; j++) {
                    ffma2(s2[i][j], qp[i].x, kp[j].x);
                    ffma2(s2[i][j], qp[i].y, kp[j].y);
                }
        }

        float s[4][4];
        #pragma unroll
        for (int i = 0; i < 4; i++)
            #pragma unroll
            for (int j = 0; j < 4; j++) {
                float lo, hi;
                upk2(s2[i][j], lo, hi);
                s[i][j] = lo + hi;
            }

        // online softmax (row stats replicated across the 16 tx threads)
        #pragma unroll
        for (int i = 0; i < 4; i++) {
            float cm = fmaxf(fmaxf(s[i][0], s[i][1]), fmaxf(s[i][2], s[i][3]));
            #pragma unroll
            for (int o = 8; o >= 1; o >>= 1)
                cm = fmaxf(cm, __shfl_xor_sync(0xffffffffu, cm, o));
            float mn = fmaxf(m_i[i], cm);
            float alpha = __expf(m_i[i] - mn);
            float p0 = __expf(s[i][0] - mn);
            float p1 = __expf(s[i][1] - mn);
            float p2 = __expf(s[i][2] - mn);
            float p3 = __expf(s[i][3] - mn);
            float rs = (p0 + p1) + (p2 + p3);
            #pragma unroll
            for (int o = 8; o >= 1; o >>= 1)
                rs += __shfl_xor_sync(0xffffffffu, rs, o);
            l_i[i] = l_i[i] * alpha + rs;
            m_i[i] = mn;
            unsigned long long ap = pk2(alpha, alpha);
            fmul2(o2[i][0], ap);
            fmul2(o2[i][1], ap);
            *(float4*)&Ps[(ty * 4 + i) * PAD + tx * 4] = make_float4(p0, p1, p2, p3);
        }
        __syncthreads();

        // O += P V (paired over output cols)
        #pragma unroll
        for (int c0 = 0; c0 < 64; c0 += 4) {
            float4 pv[4];
            #pragma unroll
            for (int i = 0; i < 4; i++)
                pv[i] = *(const float4*)&Ps[(ty * 4 + i) * PAD + c0];
            #pragma unroll
            for (int cc = 0; cc < 4; cc++) {
                ulonglong2 vv = *(const ulonglong2*)&Vs[(c0 + cc) * PAD + tx * 4];
                float pr[4] = {pv[0].x, pv[1].x, pv[2].x, pv[3].x};
                // select the cc-th component of each pv
                if (cc == 1) { pr[0] = pv[0].y; pr[1] = pv[1].y; pr[2] = pv[2].y; pr[3] = pv[3].y; }
                if (cc == 2) { pr[0] = pv[0].z; pr[1] = pv[1].z; pr[2] = pv[2].z; pr[3] = pv[3].z; }
                if (cc == 3) { pr[0] = pv[0].w; pr[1] = pv[1].w; pr[2] = pv[2].w; pr[3] = pv[3].w; }
                #pragma unroll
                for (int i = 0; i < 4; i++) {
                    unsigned long long pd = pk2(pr[i], pr[i]);
                    ffma2(o2[i][0], pd, vv.x);
                    ffma2(o2[i][1], pd, vv.y);
                }
            }
        }
    }

    // finalize: O / l, write to [b][n][h*64+d]
    #pragma unroll
    for (int i = 0; i < 4; i++) {
        float inv = 1.0f / l_i[i];
        float o0, o1, o2v, o3;
        upk2(o2[i][0], o0, o1);
        upk2(o2[i][1], o2v, o3);
        int n = q0 + ty * 4 + i;
        float4 outv = make_float4(o0 * inv, o1 * inv, o2v * inv, o3 * inv);
        *(float4*)(g_Oc + ((size_t)(b * SEQ + n)) * CD + h * DH + tx * 4) = outv;
    }
}

// ---------------------------------------------------------------------------
// Output GEMM: out[8192x512] = g_Oc @ Wo + bo
// ---------------------------------------------------------------------------
__global__ __launch_bounds__(256) void out_gemm(
    const float* __restrict__ Wo, const float* __restrict__ bo,
    float* __restrict__ out)
{
    __shared__ float As[8][128];
    __shared__ float Ws[8][128];

    const int tid = threadIdx.x;
    const int tx  = tid & 15;
    const int ty  = tid >> 4;
    const int row0 = blockIdx.y * 128;
    const int col0 = blockIdx.x * 128;

    const int arow = tid >> 1;
    const int acol = (tid & 1) * 4;
    const int wrow = tid >> 5;
    const int wcol = (tid & 31) * 4;

    unsigned long long c2[8][4];
    #pragma unroll
    for (int i = 0; i < 8; i++)
        #pragma unroll
        for (int j = 0; j < 4; j++) c2[i][j] = 0ull;

    for (int k0 = 0; k0 < CD; k0 += 8) {
        float4 av = *(const float4*)(g_Oc + (size_t)(row0 + arow) * CD + k0 + acol);
        float4 wv = *(const float4*)(Wo + (size_t)(k0 + wrow) * CD + col0 + wcol);
        __syncthreads();
        As[acol + 0][arow] = av.x;
        As[acol + 1][arow] = av.y;
        As[acol + 2][arow] = av.z;
        As[acol + 3][arow] = av.w;
        *(float4*)&Ws[wrow][wcol] = wv;
        __syncthreads();

        #pragma unroll
        for (int kk = 0; kk < 8; kk++) {
            float4 a0 = *(const float4*)&As[kk][ty * 4];
            float4 a1 = *(const float4*)&As[kk][64 + ty * 4];
            ulonglong2 b0 = *(const ulonglong2*)&Ws[kk][tx * 4];
            ulonglong2 b1 = *(const ulonglong2*)&Ws[kk][64 + tx * 4];
            float a[8] = {a0.x, a0.y, a0.z, a0.w, a1.x, a1.y, a1.z, a1.w};
            unsigned long long bp[4] = {b0.x, b0.y, b1.x, b1.y};
            #pragma unroll
            for (int i = 0; i < 8; i++) {
                unsigned long long ad = pk2(a[i], a[i]);
                #pragma unroll
                for (int j = 0; j < 4; j++) ffma2(c2[i][j], ad, bp[j]);
            }
        }
    }

    #pragma unroll
    for (int i = 0; i < 8; i++) {
        int R = row0 + ((i < 4) ? (ty * 4 + i) : (64 + ty * 4 + (i - 4)));
        float c[8];
        #pragma unroll
        for (int j = 0; j < 4; j++) upk2(c2[i][j], c[2 * j], c[2 * j + 1]);
        #pragma unroll
        for (int j = 0; j < 8; j++) {
            int col = col0 + ((j < 4) ? (tx * 4 + j) : (64 + tx * 4 + (j - 4)));
            out[(size_t)R * CD + col] = c[j] + bo[col];
        }
    }
}

// ---------------------------------------------------------------------------
extern "C" void kernel_launch(void* const* d_in, const int* in_sizes, int n_in,
                              void* d_out, int out_size)
{
    const float* x   = (const float*)d_in[0];
    const float* ctx = (const float*)d_in[1];
    const float* Wq  = (const float*)d_in[2];
    const float* Wk  = (const float*)d_in[3];
    const float* Wv  = (const float*)d_in[4];
    const float* Wo  = (const float*)d_in[5];
    const float* bo  = (const float*)d_in[6];
    float* out = (float*)d_out;

    cudaFuncSetAttribute(attn_kernel,
                         cudaFuncAttributeMaxDynamicSharedMemorySize, ATTN_SMEM);

    proj_gemm<<<dim3(4, 64, 3), 256>>>(x, ctx, Wq, Wk, Wv);
    attn_kernel<<<dim3(SEQ / 64, HH, BB), 256, ATTN_SMEM>>>();
    out_gemm<<<dim3(4, 64), 256>>>(Wo, bo, out);
}

// round 4
// speedup vs baseline: 3.5486x; 3.5454x over previous
#include <cuda_runtime.h>
#include <cuda_bf16.h>
#include <stdint.h>

// ===========================================================================
// CrossAttention via mma.sync bf16 split(hi/lo), fp32 accumulate.
// (tcgen05 unavailable: harness PTX targets sm_100, not sm_100a)
// B=4, N=M=2048, H=8, D=64, QUERY_DIM=INNER=512.
// ===========================================================================

#define BB   4
#define SEQ  2048
#define HH   8
#define DH   64
#define CD   512
#define ROWS 8192
#define BHD  (BB*HH*SEQ*DH)

__device__ __nv_bfloat16 g_xh[ROWS*CD], g_xl[ROWS*CD];
__device__ __nv_bfloat16 g_ch[ROWS*CD], g_cl[ROWS*CD];
__device__ __nv_bfloat16 g_wh[4][CD*CD], g_wl[4][CD*CD];   // [n][k] transposed
__device__ __nv_bfloat16 g_Qh[BHD], g_Ql[BHD];             // [bh][n][64] (pre-scaled 1/8)
__device__ __nv_bfloat16 g_Kh[BHD], g_Kl[BHD];             // [bh][m][64]
__device__ __nv_bfloat16 g_Vh[BHD], g_Vl[BHD];             // [bh][d][m]  (transposed)
__device__ __nv_bfloat16 g_Oh[ROWS*CD], g_Ol[ROWS*CD];     // [row][512]

// ---------------------------------------------------------------------------
__device__ __forceinline__ uint32_t smem_u32(const void* p) {
    uint32_t a;
    asm("{ .reg .u64 t; cvta.to.shared.u64 t, %1; cvt.u32.u64 %0, t; }"
        : "=r"(a) : "l"(p));
    return a;
}
__device__ __forceinline__ uint32_t swz64(uint32_t b)  { return b ^ (((b >> 7) & 3u) << 4); }
__device__ __forceinline__ uint32_t swz128(uint32_t b) { return b ^ (((b >> 7) & 7u) << 4); }

__device__ __forceinline__ void cpa16(uint32_t d, const void* s) {
    asm volatile("cp.async.cg.shared.global [%0], [%1], 16;" :: "r"(d), "l"(s));
}
#define CP_COMMIT  asm volatile("cp.async.commit_group;" ::: "memory")
#define CP_WAIT(n) asm volatile("cp.async.wait_group %0;" :: "n"(n) : "memory")

__device__ __forceinline__ void ldm4(uint32_t* r, uint32_t a) {
    asm volatile("ldmatrix.sync.aligned.m8n8.x4.shared.b16 {%0,%1,%2,%3}, [%4];"
                 : "=r"(r[0]), "=r"(r[1]), "=r"(r[2]), "=r"(r[3]) : "r"(a));
}
__device__ __forceinline__ void mma_bf16(float* c, const uint32_t* a, const uint32_t* b) {
    asm volatile("mma.sync.aligned.m16n8k16.row.col.f32.bf16.bf16.f32 "
                 "{%0,%1,%2,%3}, {%4,%5,%6,%7}, {%8,%9}, {%0,%1,%2,%3};"
                 : "+f"(c[0]), "+f"(c[1]), "+f"(c[2]), "+f"(c[3])
                 : "r"(a[0]), "r"(a[1]), "r"(a[2]), "r"(a[3]), "r"(b[0]), "r"(b[1]));
}
__device__ __forceinline__ void split2(float a, float b, uint32_t& h, uint32_t& l) {
    __nv_bfloat16 ha = __float2bfloat16(a), hb = __float2bfloat16(b);
    float ra = a - __bfloat162float(ha), rb = b - __bfloat162float(hb);
    __nv_bfloat16 la = __float2bfloat16(ra), lb = __float2bfloat16(rb);
    h = (uint32_t)__bfloat16_as_ushort(ha) | ((uint32_t)__bfloat16_as_ushort(hb) << 16);
    l = (uint32_t)__bfloat16_as_ushort(la) | ((uint32_t)__bfloat16_as_ushort(lb) << 16);
}
__device__ __forceinline__ void splitf(float x, uint16_t& hb, uint16_t& lb) {
    __nv_bfloat16 h = __float2bfloat16(x);
    hb = __bfloat16_as_ushort(h);
    __nv_bfloat16 l = __float2bfloat16(x - __bfloat162float(h));
    lb = __bfloat16_as_ushort(l);
}

// ---------------------------------------------------------------------------
// cvt kernels
// ---------------------------------------------------------------------------
__global__ __launch_bounds__(256) void cvt_act(const float* __restrict__ x,
                                               const float* __restrict__ c) {
    int i = blockIdx.x * 256 + threadIdx.x;       // per float4
    const int T = ROWS * CD / 4;
    const float* src; __nv_bfloat16 *dh, *dl; int j;
    if (i < T) { src = x; dh = g_xh; dl = g_xl; j = i; }
    else       { src = c; dh = g_ch; dl = g_cl; j = i - T; }
    float4 v = ((const float4*)src)[j];
    uint16_t h0,l0,h1,l1,h2,l2,h3,l3;
    splitf(v.x,h0,l0); splitf(v.y,h1,l1); splitf(v.z,h2,l2); splitf(v.w,h3,l3);
    ((uint2*)dh)[j] = make_uint2((uint32_t)h0 | ((uint32_t)h1 << 16),
                                 (uint32_t)h2 | ((uint32_t)h3 << 16));
    ((uint2*)dl)[j] = make_uint2((uint32_t)l0 | ((uint32_t)l1 << 16),
                                 (uint32_t)l2 | ((uint32_t)l3 << 16));
}

__global__ __launch_bounds__(256) void cvt_w(const float* __restrict__ Wq,
                                             const float* __restrict__ Wk,
                                             const float* __restrict__ Wv,
                                             const float* __restrict__ Wo) {
    int i = blockIdx.x * 256 + threadIdx.x;       // 4*512*512
    int w = i >> 18; int rem = i & 262143;
    int k = rem >> 9; int n = rem & 511;
    const float* W = (w == 0) ? Wq : (w == 1) ? Wk : (w == 2) ? Wv : Wo;
    uint16_t hb, lb; splitf(W[k * CD + n], hb, lb);
    ((uint16_t*)g_wh[w])[n * CD + k] = hb;        // [n][k]
    ((uint16_t*)g_wl[w])[n * CD + k] = lb;
}

// ---------------------------------------------------------------------------
// GEMM core: C[128x128] tile = A[128x512] * B(nk)[128x512]^T, split 3-combo.
// smem stage: AH 0, AL 8192, BH 16384, BL 24576; 2 stages (64KB).
// 8 warps: wm=wid>>1 (4), wn=wid&1 (2); warp tile 32x64.
// ---------------------------------------------------------------------------
#define G_LOAD(Agh, Agl, Bgh, Bgl, s, kt) do {                                  \
    const int _k0 = (kt) * 32;                                                  \
    const uint32_t _bs = sb + (s) * 32768;                                      \
    const int _r0 = tid >> 2, _ce = (tid & 3) * 8;                              \
    {   int _r = _r0;                                                           \
        uint32_t _so = swz64((uint32_t)(_r * 64 + (tid & 3) * 16));             \
        size_t _ga = (size_t)(row0 + _r) * CD + _k0 + _ce;                      \
        size_t _gb = (size_t)(col0 + _r) * CD + _k0 + _ce;                      \
        cpa16(_bs + _so,         (Agh) + _ga); cpa16(_bs +  8192 + _so, (Agl) + _ga); \
        cpa16(_bs + 16384 + _so, (Bgh) + _gb); cpa16(_bs + 24576 + _so, (Bgl) + _gb); } \
    {   int _r = _r0 + 64;                                                      \
        uint32_t _so = swz64((uint32_t)(_r * 64 + (tid & 3) * 16));             \
        size_t _ga = (size_t)(row0 + _r) * CD + _k0 + _ce;                      \
        size_t _gb = (size_t)(col0 + _r) * CD + _k0 + _ce;                      \
        cpa16(_bs + _so,         (Agh) + _ga); cpa16(_bs +  8192 + _so, (Agl) + _ga); \
        cpa16(_bs + 16384 + _so, (Bgh) + _gb); cpa16(_bs + 24576 + _so, (Bgl) + _gb); } \
} while (0)

#define G_COMPUTE(s) do {                                                       \
    const uint32_t _bs = sb + (s) * 32768;                                      \
    _Pragma("unroll")                                                           \
    for (int ks = 0; ks < 2; ks++) {                                            \
        uint32_t ah[2][4], al[2][4];                                            \
        _Pragma("unroll")                                                       \
        for (int mf = 0; mf < 2; mf++) {                                        \
            uint32_t rel = swz64((uint32_t)((wm*32 + mf*16 + (lane & 15)) * 64  \
                                 + (lane >> 4) * 16 + ks * 32));                \
            ldm4(ah[mf], _bs + rel);                                            \
            ldm4(al[mf], _bs + 8192 + rel);                                     \
        }                                                                       \
        uint32_t bh[8][2], bl[8][2];                                            \
        _Pragma("unroll")                                                       \
        for (int nt = 0; nt < 4; nt++) {                                        \
            uint32_t rel = swz64((uint32_t)((wn*64 + nt*16 + (lane & 15)) * 64  \
                                 + (lane >> 4) * 16 + ks * 32));                \
            uint32_t r[4];                                                      \
            ldm4(r, _bs + 16384 + rel);                                         \
            bh[2*nt][0]=r[0]; bh[2*nt][1]=r[2]; bh[2*nt+1][0]=r[1]; bh[2*nt+1][1]=r[3]; \
            ldm4(r, _bs + 24576 + rel);                                         \
            bl[2*nt][0]=r[0]; bl[2*nt][1]=r[2]; bl[2*nt+1][0]=r[1]; bl[2*nt+1][1]=r[3]; \
        }                                                                       \
        _Pragma("unroll")                                                       \
        for (int mf = 0; mf < 2; mf++)                                          \
            _Pragma("unroll")                                                   \
            for (int nf = 0; nf < 8; nf++) {                                    \
                mma_bf16(acc[mf][nf], ah[mf], bh[nf]);                          \
                mma_bf16(acc[mf][nf], ah[mf], bl[nf]);                          \
                mma_bf16(acc[mf][nf], al[mf], bh[nf]);                          \
            }                                                                   \
    }                                                                           \
} while (0)

__global__ __launch_bounds__(256) void proj_mma() {
    extern __shared__ __align__(128) char smc[];
    const uint32_t sb = smem_u32(smc);
    const int tid = threadIdx.x, lane = tid & 31, wid = tid >> 5;
    const int wm = wid >> 1, wn = wid & 1;
    const int z = blockIdx.z;
    const int row0 = blockIdx.y * 128, col0 = blockIdx.x * 128;
    const __nv_bfloat16* Agh = (z == 0) ? g_xh : g_ch;
    const __nv_bfloat16* Agl = (z == 0) ? g_xl : g_cl;
    const __nv_bfloat16* Bgh = g_wh[z];
    const __nv_bfloat16* Bgl = g_wl[z];

    float acc[2][8][4];
    #pragma unroll
    for (int i = 0; i < 2; i++)
        #pragma unroll
        for (int j = 0; j < 8; j++)
            #pragma unroll
            for (int k = 0; k < 4; k++) acc[i][j][k] = 0.f;

    G_LOAD(Agh, Agl, Bgh, Bgl, 0, 0); CP_COMMIT;
    for (int kt = 0; kt < 16; kt++) {
        if (kt < 15) { G_LOAD(Agh, Agl, Bgh, Bgl, (kt + 1) & 1, kt + 1); CP_COMMIT; CP_WAIT(1); }
        else CP_WAIT(0);
        __syncthreads();
        G_COMPUTE(kt & 1);
        __syncthreads();
    }

    const float scale = (z == 0) ? 0.125f : 1.0f;
    #pragma unroll
    for (int mf = 0; mf < 2; mf++)
        #pragma unroll
        for (int nf = 0; nf < 8; nf++) {
            int rr = row0 + wm * 32 + mf * 16 + (lane >> 2);
            int cc = col0 + wn * 64 + nf * 8 + (lane & 3) * 2;
            #pragma unroll
            for (int hf = 0; hf < 2; hf++) {
                int R = rr + hf * 8;
                float v0 = acc[mf][nf][hf * 2 + 0] * scale;
                float v1 = acc[mf][nf][hf * 2 + 1] * scale;
                int b = R >> 11, n = R & 2047, hh = cc >> 6, d = cc & 63;
                uint32_t hv, lv; split2(v0, v1, hv, lv);
                if (z < 2) {
                    __nv_bfloat16* Dh = (z == 0) ? g_Qh : g_Kh;
                    __nv_bfloat16* Dl = (z == 0) ? g_Ql : g_Kl;
                    size_t o = ((size_t)(b * HH + hh) * SEQ + n) * DH + d;
                    *(uint32_t*)(Dh + o) = hv;
                    *(uint32_t*)(Dl + o) = lv;
                } else {
                    size_t o = ((size_t)(b * HH + hh) * DH + d) * SEQ + n;
                    ((uint16_t*)g_Vh)[o] = (uint16_t)hv;  ((uint16_t*)g_Vh)[o + SEQ] = (uint16_t)(hv >> 16);
                    ((uint16_t*)g_Vl)[o] = (uint16_t)lv;  ((uint16_t*)g_Vl)[o + SEQ] = (uint16_t)(lv >> 16);
                }
            }
        }
}

__global__ __launch_bounds__(256) void out_mma(const float* __restrict__ bo,
                                               float* __restrict__ out) {
    extern __shared__ __align__(128) char smc[];
    const uint32_t sb = smem_u32(smc);
    const int tid = threadIdx.x, lane = tid & 31, wid = tid >> 5;
    const int wm = wid >> 1, wn = wid & 1;
    const int row0 = blockIdx.y * 128, col0 = blockIdx.x * 128;

    float acc[2][8][4];
    #pragma unroll
    for (int i = 0; i < 2; i++)
        #pragma unroll
        for (int j = 0; j < 8; j++)
            #pragma unroll
            for (int k = 0; k < 4; k++) acc[i][j][k] = 0.f;

    G_LOAD(g_Oh, g_Ol, g_wh[3], g_wl[3], 0, 0); CP_COMMIT;
    for (int kt = 0; kt < 16; kt++) {
        if (kt < 15) { G_LOAD(g_Oh, g_Ol, g_wh[3], g_wl[3], (kt + 1) & 1, kt + 1); CP_COMMIT; CP_WAIT(1); }
        else CP_WAIT(0);
        __syncthreads();
        G_COMPUTE(kt & 1);
        __syncthreads();
    }

    #pragma unroll
    for (int mf = 0; mf < 2; mf++)
        #pragma unroll
        for (int nf = 0; nf < 8; nf++) {
            int rr = row0 + wm * 32 + mf * 16 + (lane >> 2);
            int cc = col0 + wn * 64 + nf * 8 + (lane & 3) * 2;
            #pragma unroll
            for (int hf = 0; hf < 2; hf++) {
                int R = rr + hf * 8;
                float2 v;
                v.x = acc[mf][nf][hf * 2 + 0] + __ldg(&bo[cc]);
                v.y = acc[mf][nf][hf * 2 + 1] + __ldg(&bo[cc + 1]);
                *(float2*)(out + (size_t)R * CD + cc) = v;
            }
        }
}

// ---------------------------------------------------------------------------
// attention: 128 q/CTA, 32 chunks of 64 keys, O in registers, unnormalized exp.
// smem: QH 0, QL 16384; KV stages at 32768 + s*32768 {KH,KL,VH,VL} (96KB).
// 8 warps: warp = 16 q rows, full 64 keys / 64 d.
// ---------------------------------------------------------------------------
#define KV_LOAD(s, jj) do {                                                     \
    const int _m0 = (jj) * 64;                                                  \
    const uint32_t _bs = sb + 32768 + (s) * 32768;                              \
    {   int _ch = tid; int _r = _ch >> 3, _c = _ch & 7;                         \
        uint32_t _so = swz128((uint32_t)(_r * 128 + _c * 16));                  \
        size_t _gk = ((size_t)bh * SEQ + _m0 + _r) * DH + _c * 8;               \
        size_t _gv = ((size_t)bh * DH + _r) * SEQ + _m0 + _c * 8;               \
        cpa16(_bs + _so,         g_Kh + _gk); cpa16(_bs +  8192 + _so, g_Kl + _gk); \
        cpa16(_bs + 16384 + _so, g_Vh + _gv); cpa16(_bs + 24576 + _so, g_Vl + _gv); } \
    {   int _ch = 256 + tid; int _r = _ch >> 3, _c = _ch & 7;                   \
        uint32_t _so = swz128((uint32_t)(_r * 128 + _c * 16));                  \
        size_t _gk = ((size_t)bh * SEQ + _m0 + _r) * DH + _c * 8;               \
        size_t _gv = ((size_t)bh * DH + _r) * SEQ + _m0 + _c * 8;               \
        cpa16(_bs + _so,         g_Kh + _gk); cpa16(_bs +  8192 + _so, g_Kl + _gk); \
        cpa16(_bs + 16384 + _so, g_Vh + _gv); cpa16(_bs + 24576 + _so, g_Vl + _gv); } \
} while (0)

__global__ __launch_bounds__(256) void attn_mma() {
    extern __shared__ __align__(128) char smc[];
    const uint32_t sb = smem_u32(smc);
    const int tid = threadIdx.x, lane = tid & 31, wid = tid >> 5;
    const int q0 = blockIdx.x * 128, h = blockIdx.y, b = blockIdx.z;
    const int bh = b * HH + h;

    // Q tile (persistent): 1024 chunks per array, 4/thread
    #pragma unroll
    for (int t = 0; t < 4; t++) {
        int ch = t * 256 + tid; int r = ch >> 3, c = ch & 7;
        uint32_t so = swz128((uint32_t)(r * 128 + c * 16));
        size_t g = ((size_t)bh * SEQ + q0 + r) * DH + c * 8;
        cpa16(sb + so,         g_Qh + g);
        cpa16(sb + 16384 + so, g_Ql + g);
    }
    KV_LOAD(0, 0); CP_COMMIT;

    float oacc[8][4];
    #pragma unroll
    for (int i = 0; i < 8; i++)
        #pragma unroll
        for (int k = 0; k < 4; k++) oacc[i][k] = 0.f;
    float l0 = 0.f, l1 = 0.f;

    for (int j = 0; j < 32; j++) {
        if (j < 31) { KV_LOAD((j + 1) & 1, j + 1); CP_COMMIT; CP_WAIT(1); }
        else CP_WAIT(0);
        __syncthreads();
        const uint32_t bs = sb + 32768 + (j & 1) * 32768;

        float sacc[8][4];
        #pragma unroll
        for (int i = 0; i < 8; i++)
            #pragma unroll
            for (int k = 0; k < 4; k++) sacc[i][k] = 0.f;

        // S = Q K^T  (k over d, 4 k16-steps, 3 split combos)
        #pragma unroll
        for (int ks = 0; ks < 4; ks++) {
            uint32_t qh[4], ql[4];
            uint32_t relq = swz128((uint32_t)((wid * 16 + (lane & 15)) * 128
                                   + (lane >> 4) * 16 + ks * 32));
            ldm4(qh, sb + relq);
            ldm4(ql, sb + 16384 + relq);
            uint32_t kh[8][2], kl[8][2];
            #pragma unroll
            for (int nt = 0; nt < 4; nt++) {
                uint32_t rel = swz128((uint32_t)((nt * 16 + (lane & 15)) * 128
                                      + (lane >> 4) * 16 + ks * 32));
                uint32_t r[4];
                ldm4(r, bs + rel);
                kh[2*nt][0]=r[0]; kh[2*nt][1]=r[2]; kh[2*nt+1][0]=r[1]; kh[2*nt+1][1]=r[3];
                ldm4(r, bs + 8192 + rel);
                kl[2*nt][0]=r[0]; kl[2*nt][1]=r[2]; kl[2*nt+1][0]=r[1]; kl[2*nt+1][1]=r[3];
            }
            #pragma unroll
            for (int nf = 0; nf < 8; nf++) {
                mma_bf16(sacc[nf], qh, kh[nf]);
                mma_bf16(sacc[nf], qh, kl[nf]);
                mma_bf16(sacc[nf], ql, kh[nf]);
            }
        }

        // unnormalized exp -> P fragments (C-frag layout == A-frag layout)
        uint32_t pah[4][4], pal[4][4];
        #pragma unroll
        for (int kk = 0; kk < 4; kk++) {
            float e0 = __expf(sacc[2*kk][0]),   e1 = __expf(sacc[2*kk][1]);
            float e2 = __expf(sacc[2*kk][2]),   e3 = __expf(sacc[2*kk][3]);
            float e4 = __expf(sacc[2*kk+1][0]), e5 = __expf(sacc[2*kk+1][1]);
            float e6 = __expf(sacc[2*kk+1][2]), e7 = __expf(sacc[2*kk+1][3]);
            l0 += (e0 + e1) + (e4 + e5);
            l1 += (e2 + e3) + (e6 + e7);
            split2(e0, e1, pah[kk][0], pal[kk][0]);
            split2(e2, e3, pah[kk][1], pal[kk][1]);
            split2(e4, e5, pah[kk][2], pal[kk][2]);
            split2(e6, e7, pah[kk][3], pal[kk][3]);
        }

        // O += P V   (k over keys, V^T stored [d][m] -> B frags non-trans)
        #pragma unroll
        for (int ks = 0; ks < 4; ks++) {
            uint32_t vh[8][2], vl[8][2];
            #pragma unroll
            for (int nt = 0; nt < 4; nt++) {
                uint32_t rel = swz128((uint32_t)((nt * 16 + (lane & 15)) * 128
                                      + (lane >> 4) * 16 + ks * 32));
                uint32_t r[4];
                ldm4(r, bs + 16384 + rel);
                vh[2*nt][0]=r[0]; vh[2*nt][1]=r[2]; vh[2*nt+1][0]=r[1]; vh[2*nt+1][1]=r[3];
                ldm4(r, bs + 24576 + rel);
                vl[2*nt][0]=r[0]; vl[2*nt][1]=r[2]; vl[2*nt+1][0]=r[1]; vl[2*nt+1][1]=r[3];
            }
            #pragma unroll
            for (int nf = 0; nf < 8; nf++) {
                mma_bf16(oacc[nf], pah[ks], vh[nf]);
                mma_bf16(oacc[nf], pah[ks], vl[nf]);
                mma_bf16(oacc[nf], pal[ks], vh[nf]);
            }
        }
        __syncthreads();
    }

    // row sums live on the lane-quad (lanes sharing lane>>2): reduce xor 1,2
    l0 += __shfl_xor_sync(0xffffffffu, l0, 1);
    l0 += __shfl_xor_sync(0xffffffffu, l0, 2);
    l1 += __shfl_xor_sync(0xffffffffu, l1, 1);
    l1 += __shfl_xor_sync(0xffffffffu, l1, 2);
    const float inv0 = 1.f / l0, inv1 = 1.f / l1;

    const int n0 = q0 + wid * 16 + (lane >> 2);
    #pragma unroll
    for (int nf = 0; nf < 8; nf++) {
        int d = nf * 8 + (lane & 3) * 2;
        int col = h * DH + d;
        uint32_t hv, lv;
        split2(oacc[nf][0] * inv0, oacc[nf][1] * inv0, hv, lv);
        size_t o0 = ((size_t)b * SEQ + n0) * CD + col;
        *(uint32_t*)(g_Oh + o0) = hv; *(uint32_t*)(g_Ol + o0) = lv;
        split2(oacc[nf][2] * inv1, oacc[nf][3] * inv1, hv, lv);
        size_t o1 = ((size_t)b * SEQ + n0 + 8) * CD + col;
        *(uint32_t*)(g_Oh + o1) = hv; *(uint32_t*)(g_Ol + o1) = lv;
    }
}

// ---------------------------------------------------------------------------
extern "C" void kernel_launch(void* const* d_in, const int* in_sizes, int n_in,
                              void* d_out, int out_size) {
    const float* x   = (const float*)d_in[0];
    const float* ctx = (const float*)d_in[1];
    const float* Wq  = (const float*)d_in[2];
    const float* Wk  = (const float*)d_in[3];
    const float* Wv  = (const float*)d_in[4];
    const float* Wo  = (const float*)d_in[5];
    const float* bo  = (const float*)d_in[6];
    float* out = (float*)d_out;

    static int inited = 0;
    if (!inited) {
        cudaFuncSetAttribute(proj_mma, cudaFuncAttributeMaxDynamicSharedMemorySize, 65536);
        cudaFuncSetAttribute(out_mma,  cudaFuncAttributeMaxDynamicSharedMemorySize, 65536);
        cudaFuncSetAttribute(attn_mma, cudaFuncAttributeMaxDynamicSharedMemorySize, 98304);
        inited = 1;
    }

    cvt_act<<<2 * ROWS * CD / 4 / 256, 256>>>(x, ctx);
    cvt_w<<<4 * CD * CD / 256, 256>>>(Wq, Wk, Wv, Wo);
    proj_mma<<<dim3(4, 64, 3), 256, 65536>>>();
    attn_mma<<<dim3(SEQ / 128, HH, BB), 256, 98304>>>();
    out_mma<<<dim3(4, 64), 256, 65536>>>(bo, out);
}

// round 5
// speedup vs baseline: 4.7775x; 1.3463x over previous
#include <cuda_runtime.h>
#include <cuda_fp16.h>
#include <stdint.h>

// ===========================================================================
// CrossAttention via mma.sync fp16 2-combo (A split hi/lo, B single), fp32 acc.
// B=4, N=M=2048, H=8, D=64, QUERY_DIM=INNER=512.
// ===========================================================================

#define BB   4
#define SEQ  2048
#define HH   8
#define DH   64
#define CD   512
#define ROWS 8192
#define BHD  (BB*HH*SEQ*DH)

__device__ __half g_xh[ROWS*CD], g_xl[ROWS*CD];
__device__ __half g_ch[ROWS*CD], g_cl[ROWS*CD];
__device__ __half g_w[4][CD*CD];                 // [n][k] transposed, single fp16
__device__ __half g_Qh[BHD], g_Ql[BHD];          // [bh][n][64] UNSCALED, split
__device__ __half g_Kv[BHD];                     // [bh][m][64] single
__device__ __half g_Vv[BHD];                     // [bh][d][m]  single, transposed
__device__ __half g_Oh[ROWS*CD], g_Ol[ROWS*CD];  // [row][512], O*64 split

// ---------------------------------------------------------------------------
__device__ __forceinline__ uint32_t smem_u32(const void* p) {
    uint32_t a;
    asm("{ .reg .u64 t; cvta.to.shared.u64 t, %1; cvt.u32.u64 %0, t; }"
        : "=r"(a) : "l"(p));
    return a;
}
__device__ __forceinline__ uint32_t swz128(uint32_t b) { return b ^ (((b >> 7) & 7u) << 4); }

__device__ __forceinline__ void cpa16(uint32_t d, const void* s) {
    asm volatile("cp.async.cg.shared.global [%0], [%1], 16;" :: "r"(d), "l"(s));
}
#define CP_COMMIT  asm volatile("cp.async.commit_group;" ::: "memory")
#define CP_WAIT(n) asm volatile("cp.async.wait_group %0;" :: "n"(n) : "memory")

__device__ __forceinline__ void ldm4(uint32_t* r, uint32_t a) {
    asm volatile("ldmatrix.sync.aligned.m8n8.x4.shared.b16 {%0,%1,%2,%3}, [%4];"
                 : "=r"(r[0]), "=r"(r[1]), "=r"(r[2]), "=r"(r[3]) : "r"(a));
}
__device__ __forceinline__ void mma_f16(float* c, const uint32_t* a, const uint32_t* b) {
    asm volatile("mma.sync.aligned.m16n8k16.row.col.f32.f16.f16.f32 "
                 "{%0,%1,%2,%3}, {%4,%5,%6,%7}, {%8,%9}, {%0,%1,%2,%3};"
                 : "+f"(c[0]), "+f"(c[1]), "+f"(c[2]), "+f"(c[3])
                 : "r"(a[0]), "r"(a[1]), "r"(a[2]), "r"(a[3]), "r"(b[0]), "r"(b[1]));
}
__device__ __forceinline__ void split2h(float a, float b, uint32_t& h, uint32_t& l) {
    __half ha = __float2half_rn(a), hb = __float2half_rn(b);
    float ra = a - __half2float(ha), rb = b - __half2float(hb);
    __half la = __float2half_rn(ra), lb = __float2half_rn(rb);
    h = (uint32_t)__half_as_ushort(ha) | ((uint32_t)__half_as_ushort(hb) << 16);
    l = (uint32_t)__half_as_ushort(la) | ((uint32_t)__half_as_ushort(lb) << 16);
}
__device__ __forceinline__ void splith(float x, uint16_t& hb, uint16_t& lb) {
    __half h = __float2half_rn(x);
    hb = __half_as_ushort(h);
    lb = __half_as_ushort(__float2half_rn(x - __half2float(h)));
}

// ---------------------------------------------------------------------------
// cvt kernels
// ---------------------------------------------------------------------------
__global__ __launch_bounds__(256) void cvt_act(const float* __restrict__ x,
                                               const float* __restrict__ c) {
    int i = blockIdx.x * 256 + threadIdx.x;       // per float4
    const int T = ROWS * CD / 4;
    const float* src; __half *dh, *dl; int j;
    if (i < T) { src = x; dh = g_xh; dl = g_xl; j = i; }
    else       { src = c; dh = g_ch; dl = g_cl; j = i - T; }
    float4 v = ((const float4*)src)[j];
    uint16_t h0,l0,h1,l1,h2,l2,h3,l3;
    splith(v.x,h0,l0); splith(v.y,h1,l1); splith(v.z,h2,l2); splith(v.w,h3,l3);
    ((uint2*)dh)[j] = make_uint2((uint32_t)h0 | ((uint32_t)h1 << 16),
                                 (uint32_t)h2 | ((uint32_t)h3 << 16));
    ((uint2*)dl)[j] = make_uint2((uint32_t)l0 | ((uint32_t)l1 << 16),
                                 (uint32_t)l2 | ((uint32_t)l3 << 16));
}

__global__ __launch_bounds__(256) void cvt_w(const float* __restrict__ Wq,
                                             const float* __restrict__ Wk,
                                             const float* __restrict__ Wv,
                                             const float* __restrict__ Wo) {
    int i = blockIdx.x * 256 + threadIdx.x;       // 4*512*512
    int w = i >> 18; int rem = i & 262143;
    int k = rem >> 9; int n = rem & 511;
    const float* W = (w == 0) ? Wq : (w == 1) ? Wk : (w == 2) ? Wv : Wo;
    ((uint16_t*)g_w[w])[n * CD + k] = __half_as_ushort(__float2half_rn(W[k * CD + n]));
}

// ---------------------------------------------------------------------------
// GEMM core: C[128x128] = A[128x512] (split) * B(nk)[128x512]^T (single).
// K-tile 64; stage: AH 0 (16K), AL 16K, B 32K; 2 stages (96KB total).
// 8 warps: wm=wid>>1 (4), wn=wid&1 (2); warp tile 32x64.
// ---------------------------------------------------------------------------
#define PJ_STG 49152

#define G_LOAD(Agh, Agl, Bg, s, kt) do {                                        \
    const int _k0 = (kt) * 64;                                                  \
    const uint32_t _bs = sb + (s) * PJ_STG;                                     \
    _Pragma("unroll")                                                           \
    for (int _t = 0; _t < 4; _t++) {                                            \
        int _ch = _t * 256 + tid;                                               \
        int _r = _ch >> 3, _c = _ch & 7;                                        \
        uint32_t _so = swz128((uint32_t)(_r * 128 + _c * 16));                  \
        size_t _ga = (size_t)(row0 + _r) * CD + _k0 + _c * 8;                   \
        size_t _gb = (size_t)(col0 + _r) * CD + _k0 + _c * 8;                   \
        cpa16(_bs + _so,         (Agh) + _ga);                                  \
        cpa16(_bs + 16384 + _so, (Agl) + _ga);                                  \
        cpa16(_bs + 32768 + _so, (Bg)  + _gb);                                  \
    }                                                                           \
} while (0)

#define G_COMPUTE(s) do {                                                       \
    const uint32_t _bs = sb + (s) * PJ_STG;                                     \
    _Pragma("unroll")                                                           \
    for (int ks = 0; ks < 4; ks++) {                                            \
        uint32_t ah[2][4], al[2][4];                                            \
        _Pragma("unroll")                                                       \
        for (int mf = 0; mf < 2; mf++) {                                        \
            uint32_t rel = swz128((uint32_t)((wm*32 + mf*16 + (lane & 15)) * 128 \
                                 + (lane >> 4) * 16 + ks * 32));                \
            ldm4(ah[mf], _bs + rel);                                            \
            ldm4(al[mf], _bs + 16384 + rel);                                    \
        }                                                                       \
        uint32_t bfr[8][2];                                                     \
        _Pragma("unroll")                                                       \
        for (int nt = 0; nt < 4; nt++) {                                        \
            uint32_t rel = swz128((uint32_t)((wn*64 + nt*16 + (lane & 15)) * 128 \
                                 + (lane >> 4) * 16 + ks * 32));                \
            uint32_t r[4];                                                      \
            ldm4(r, _bs + 32768 + rel);                                         \
            bfr[2*nt][0]=r[0]; bfr[2*nt][1]=r[2];                               \
            bfr[2*nt+1][0]=r[1]; bfr[2*nt+1][1]=r[3];                           \
        }                                                                       \
        _Pragma("unroll")                                                       \
        for (int mf = 0; mf < 2; mf++)                                          \
            _Pragma("unroll")                                                   \
            for (int nf = 0; nf < 8; nf++) {                                    \
                mma_f16(acc[mf][nf], ah[mf], bfr[nf]);                          \
                mma_f16(acc[mf][nf], al[mf], bfr[nf]);                          \
            }                                                                   \
    }                                                                           \
} while (0)

__global__ __launch_bounds__(256) void proj_mma() {
    extern __shared__ __align__(128) char smc[];
    const uint32_t sb = smem_u32(smc);
    const int tid = threadIdx.x, lane = tid & 31, wid = tid >> 5;
    const int wm = wid >> 1, wn = wid & 1;
    const int z = blockIdx.z;
    const int row0 = blockIdx.y * 128, col0 = blockIdx.x * 128;
    const __half* Agh = (z == 0) ? g_xh : g_ch;
    const __half* Agl = (z == 0) ? g_xl : g_cl;
    const __half* Bg  = g_w[z];

    float acc[2][8][4];
    #pragma unroll
    for (int i = 0; i < 2; i++)
        #pragma unroll
        for (int j = 0; j < 8; j++)
            #pragma unroll
            for (int k = 0; k < 4; k++) acc[i][j][k] = 0.f;

    G_LOAD(Agh, Agl, Bg, 0, 0); CP_COMMIT;
    for (int kt = 0; kt < 8; kt++) {
        if (kt < 7) { G_LOAD(Agh, Agl, Bg, (kt + 1) & 1, kt + 1); CP_COMMIT; CP_WAIT(1); }
        else CP_WAIT(0);
        __syncthreads();
        G_COMPUTE(kt & 1);
        __syncthreads();
    }

    #pragma unroll
    for (int mf = 0; mf < 2; mf++)
        #pragma unroll
        for (int nf = 0; nf < 8; nf++) {
            int rr = row0 + wm * 32 + mf * 16 + (lane >> 2);
            int cc = col0 + wn * 64 + nf * 8 + (lane & 3) * 2;
            #pragma unroll
            for (int hf = 0; hf < 2; hf++) {
                int R = rr + hf * 8;
                float v0 = acc[mf][nf][hf * 2 + 0];
                float v1 = acc[mf][nf][hf * 2 + 1];
                int b = R >> 11, n = R & 2047, hh = cc >> 6, d = cc & 63;
                if (z == 0) {            // Q: split, unscaled
                    uint32_t hv, lv; split2h(v0, v1, hv, lv);
                    size_t o = ((size_t)(b * HH + hh) * SEQ + n) * DH + d;
                    *(uint32_t*)(g_Qh + o) = hv;
                    *(uint32_t*)(g_Ql + o) = lv;
                } else if (z == 1) {     // K: single
                    uint32_t hv = (uint32_t)__half_as_ushort(__float2half_rn(v0))
                                | ((uint32_t)__half_as_ushort(__float2half_rn(v1)) << 16);
                    size_t o = ((size_t)(b * HH + hh) * SEQ + n) * DH + d;
                    *(uint32_t*)(g_Kv + o) = hv;
                } else {                 // V: single, transposed [d][m]
                    size_t o = ((size_t)(b * HH + hh) * DH + d) * SEQ + n;
                    ((uint16_t*)g_Vv)[o]       = __half_as_ushort(__float2half_rn(v0));
                    ((uint16_t*)g_Vv)[o + SEQ] = __half_as_ushort(__float2half_rn(v1));
                }
            }
        }
}

__global__ __launch_bounds__(256) void out_mma(const float* __restrict__ bo,
                                               float* __restrict__ out) {
    extern __shared__ __align__(128) char smc[];
    const uint32_t sb = smem_u32(smc);
    const int tid = threadIdx.x, lane = tid & 31, wid = tid >> 5;
    const int wm = wid >> 1, wn = wid & 1;
    const int row0 = blockIdx.y * 128, col0 = blockIdx.x * 128;

    float acc[2][8][4];
    #pragma unroll
    for (int i = 0; i < 2; i++)
        #pragma unroll
        for (int j = 0; j < 8; j++)
            #pragma unroll
            for (int k = 0; k < 4; k++) acc[i][j][k] = 0.f;

    G_LOAD(g_Oh, g_Ol, g_w[3], 0, 0); CP_COMMIT;
    for (int kt = 0; kt < 8; kt++) {
        if (kt < 7) { G_LOAD(g_Oh, g_Ol, g_w[3], (kt + 1) & 1, kt + 1); CP_COMMIT; CP_WAIT(1); }
        else CP_WAIT(0);
        __syncthreads();
        G_COMPUTE(kt & 1);
        __syncthreads();
    }

    #pragma unroll
    for (int mf = 0; mf < 2; mf++)
        #pragma unroll
        for (int nf = 0; nf < 8; nf++) {
            int rr = row0 + wm * 32 + mf * 16 + (lane >> 2);
            int cc = col0 + wn * 64 + nf * 8 + (lane & 3) * 2;
            #pragma unroll
            for (int hf = 0; hf < 2; hf++) {
                int R = rr + hf * 8;
                float2 v;
                v.x = acc[mf][nf][hf * 2 + 0] * 0.015625f + __ldg(&bo[cc]);
                v.y = acc[mf][nf][hf * 2 + 1] * 0.015625f + __ldg(&bo[cc + 1]);
                *(float2*)(out + (size_t)R * CD + cc) = v;
            }
        }
}

// ---------------------------------------------------------------------------
// attention: 128 q/CTA, 32 chunks of 64 keys, O in registers, unnormalized exp
// (1/8 scale folded into exp arg). smem: QH 0 (16K), QL 16K; 3 KV stages at
// 32768 + s*16384 {K 8K, V 8K} = 80KB. One __syncthreads per chunk.
// ---------------------------------------------------------------------------
#define KV_LOAD(s, jj) do {                                                     \
    const int _m0 = (jj) * 64;                                                  \
    const uint32_t _bs = sb + 32768 + (s) * 16384;                              \
    _Pragma("unroll")                                                           \
    for (int _t = 0; _t < 2; _t++) {                                            \
        int _ch = _t * 256 + tid;                                               \
        int _r = _ch >> 3, _c = _ch & 7;                                        \
        uint32_t _so = swz128((uint32_t)(_r * 128 + _c * 16));                  \
        size_t _gk = ((size_t)bh * SEQ + _m0 + _r) * DH + _c * 8;               \
        size_t _gv = ((size_t)bh * DH + _r) * SEQ + _m0 + _c * 8;               \
        cpa16(_bs + _so,        g_Kv + _gk);                                    \
        cpa16(_bs + 8192 + _so, g_Vv + _gv);                                    \
    }                                                                           \
} while (0)

__global__ __launch_bounds__(256) void attn_mma() {
    extern __shared__ __align__(128) char smc[];
    const uint32_t sb = smem_u32(smc);
    const int tid = threadIdx.x, lane = tid & 31, wid = tid >> 5;
    const int q0 = blockIdx.x * 128, h = blockIdx.y, b = blockIdx.z;
    const int bh = b * HH + h;

    // Q tile (persistent, split): 1024 16B-chunks per array, 4/thread
    #pragma unroll
    for (int t = 0; t < 4; t++) {
        int ch = t * 256 + tid; int r = ch >> 3, c = ch & 7;
        uint32_t so = swz128((uint32_t)(r * 128 + c * 16));
        size_t g = ((size_t)bh * SEQ + q0 + r) * DH + c * 8;
        cpa16(sb + so,         g_Qh + g);
        cpa16(sb + 16384 + so, g_Ql + g);
    }
    KV_LOAD(0, 0); CP_COMMIT;
    KV_LOAD(1, 1); CP_COMMIT;

    float oacc[8][4];
    #pragma unroll
    for (int i = 0; i < 8; i++)
        #pragma unroll
        for (int k = 0; k < 4; k++) oacc[i][k] = 0.f;
    float l0 = 0.f, l1 = 0.f;

    for (int j = 0; j < 32; j++) {
        if (j < 31) CP_WAIT(1); else CP_WAIT(0);
        __syncthreads();
        const uint32_t bs = sb + 32768 + (j % 3) * 16384;

        float sacc[8][4];
        #pragma unroll
        for (int i = 0; i < 8; i++)
            #pragma unroll
            for (int k = 0; k < 4; k++) sacc[i][k] = 0.f;

        // S = Q K^T  (A = Q split, B = K single)
        #pragma unroll
        for (int ks = 0; ks < 4; ks++) {
            uint32_t qh[4], ql[4];
            uint32_t relq = swz128((uint32_t)((wid * 16 + (lane & 15)) * 128
                                   + (lane >> 4) * 16 + ks * 32));
            ldm4(qh, sb + relq);
            ldm4(ql, sb + 16384 + relq);
            uint32_t kf[8][2];
            #pragma unroll
            for (int nt = 0; nt < 4; nt++) {
                uint32_t rel = swz128((uint32_t)((nt * 16 + (lane & 15)) * 128
                                      + (lane >> 4) * 16 + ks * 32));
                uint32_t r[4];
                ldm4(r, bs + rel);
                kf[2*nt][0]=r[0]; kf[2*nt][1]=r[2]; kf[2*nt+1][0]=r[1]; kf[2*nt+1][1]=r[3];
            }
            #pragma unroll
            for (int nf = 0; nf < 8; nf++) {
                mma_f16(sacc[nf], qh, kf[nf]);
                mma_f16(sacc[nf], ql, kf[nf]);
            }
        }

        // unnormalized exp(s/8) -> split P fragments (C layout == A layout)
        uint32_t pah[4][4], pal[4][4];
        #pragma unroll
        for (int kk = 0; kk < 4; kk++) {
            float e0 = __expf(sacc[2*kk][0]   * 0.125f), e1 = __expf(sacc[2*kk][1]   * 0.125f);
            float e2 = __expf(sacc[2*kk][2]   * 0.125f), e3 = __expf(sacc[2*kk][3]   * 0.125f);
            float e4 = __expf(sacc[2*kk+1][0] * 0.125f), e5 = __expf(sacc[2*kk+1][1] * 0.125f);
            float e6 = __expf(sacc[2*kk+1][2] * 0.125f), e7 = __expf(sacc[2*kk+1][3] * 0.125f);
            l0 += (e0 + e1) + (e4 + e5);
            l1 += (e2 + e3) + (e6 + e7);
            split2h(e0, e1, pah[kk][0], pal[kk][0]);
            split2h(e2, e3, pah[kk][1], pal[kk][1]);
            split2h(e4, e5, pah[kk][2], pal[kk][2]);
            split2h(e6, e7, pah[kk][3], pal[kk][3]);
        }

        // O += P V   (A = P split, B = V^T single [d][m])
        #pragma unroll
        for (int ks = 0; ks < 4; ks++) {
            uint32_t vf[8][2];
            #pragma unroll
            for (int nt = 0; nt < 4; nt++) {
                uint32_t rel = swz128((uint32_t)((nt * 16 + (lane & 15)) * 128
                                      + (lane >> 4) * 16 + ks * 32));
                uint32_t r[4];
                ldm4(r, bs + 8192 + rel);
                vf[2*nt][0]=r[0]; vf[2*nt][1]=r[2]; vf[2*nt+1][0]=r[1]; vf[2*nt+1][1]=r[3];
            }
            #pragma unroll
            for (int nf = 0; nf < 8; nf++) {
                mma_f16(oacc[nf], pah[ks], vf[nf]);
                mma_f16(oacc[nf], pal[ks], vf[nf]);
            }
        }

        // prefetch chunk j+2 into stage (j+2)%3 (its last readers finished
        // chunk j-1, which completed before this iteration's __syncthreads)
        if (j < 30) { KV_LOAD((j + 2) % 3, j + 2); CP_COMMIT; }
    }

    // row sums live on the lane-quad: reduce xor 1,2
    l0 += __shfl_xor_sync(0xffffffffu, l0, 1);
    l0 += __shfl_xor_sync(0xffffffffu, l0, 2);
    l1 += __shfl_xor_sync(0xffffffffu, l1, 1);
    l1 += __shfl_xor_sync(0xffffffffu, l1, 2);
    const float inv0 = 64.f / l0, inv1 = 64.f / l1;   // store O*64

    const int n0 = q0 + wid * 16 + (lane >> 2);
    #pragma unroll
    for (int nf = 0; nf < 8; nf++) {
        int d = nf * 8 + (lane & 3) * 2;
        int col = h * DH + d;
        uint32_t hv, lv;
        split2h(oacc[nf][0] * inv0, oacc[nf][1] * inv0, hv, lv);
        size_t o0 = ((size_t)b * SEQ + n0) * CD + col;
        *(uint32_t*)(g_Oh + o0) = hv; *(uint32_t*)(g_Ol + o0) = lv;
        split2h(oacc[nf][2] * inv1, oacc[nf][3] * inv1, hv, lv);
        size_t o1 = ((size_t)b * SEQ + n0 + 8) * CD + col;
        *(uint32_t*)(g_Oh + o1) = hv; *(uint32_t*)(g_Ol + o1) = lv;
    }
}

// ---------------------------------------------------------------------------
extern "C" void kernel_launch(void* const* d_in, const int* in_sizes, int n_in,
                              void* d_out, int out_size) {
    const float* x   = (const float*)d_in[0];
    const float* ctx = (const float*)d_in[1];
    const float* Wq  = (const float*)d_in[2];
    const float* Wk  = (const float*)d_in[3];
    const float* Wv  = (const float*)d_in[4];
    const float* Wo  = (const float*)d_in[5];
    const float* bo  = (const float*)d_in[6];
    float* out = (float*)d_out;

    static int inited = 0;
    if (!inited) {
        cudaFuncSetAttribute(proj_mma, cudaFuncAttributeMaxDynamicSharedMemorySize, 2 * PJ_STG);
        cudaFuncSetAttribute(out_mma,  cudaFuncAttributeMaxDynamicSharedMemorySize, 2 * PJ_STG);
        cudaFuncSetAttribute(attn_mma, cudaFuncAttributeMaxDynamicSharedMemorySize, 81920);
        inited = 1;
    }

    cvt_act<<<2 * ROWS * CD / 4 / 256, 256>>>(x, ctx);
    cvt_w<<<4 * CD * CD / 256, 256>>>(Wq, Wk, Wv, Wo);
    proj_mma<<<dim3(4, 64, 3), 256, 2 * PJ_STG>>>();
    attn_mma<<<dim3(SEQ / 128, HH, BB), 256, 81920>>>();
    out_mma<<<dim3(4, 64), 256, 2 * PJ_STG>>>(bo, out);
}

// round 8
// speedup vs baseline: 5.0527x; 1.0576x over previous
#include <cuda_runtime.h>
#include <cuda_fp16.h>
#include <stdint.h>

// ===========================================================================
// CrossAttention via mma.sync fp16 2-combo (A split hi/lo, B single), fp32 acc.
// B=4, N=M=2048, H=8, D=64, QUERY_DIM=INNER=512.
// ===========================================================================

#define BB   4
#define SEQ  2048
#define HH   8
#define DH   64
#define CD   512
#define ROWS 8192
#define BHD  (BB*HH*SEQ*DH)

__device__ __half g_xh[ROWS*CD], g_xl[ROWS*CD];
__device__ __half g_ch[ROWS*CD], g_cl[ROWS*CD];
__device__ __half g_w[4][CD*CD];                 // [n][k] transposed, single fp16
__device__ __half g_Qh[BHD], g_Ql[BHD];          // [bh][n][64] UNSCALED, split
__device__ __half g_Kv[BHD];                     // [bh][m][64] single
__device__ __half g_Vv[BHD];                     // [bh][d][m]  single, transposed
__device__ __half g_Oh[ROWS*CD], g_Ol[ROWS*CD];  // [row][512], O*64 split

// ---------------------------------------------------------------------------
__device__ __forceinline__ uint32_t smem_u32(const void* p) {
    uint32_t a;
    asm("{ .reg .u64 t; cvta.to.shared.u64 t, %1; cvt.u32.u64 %0, t; }"
        : "=r"(a) : "l"(p));
    return a;
}
__device__ __forceinline__ uint32_t swz128(uint32_t b) { return b ^ (((b >> 7) & 7u) << 4); }

__device__ __forceinline__ void cpa16(uint32_t d, const void* s) {
    asm volatile("cp.async.cg.shared.global [%0], [%1], 16;" :: "r"(d), "l"(s));
}
#define CP_COMMIT  asm volatile("cp.async.commit_group;" ::: "memory")
#define CP_WAIT(n) asm volatile("cp.async.wait_group %0;" :: "n"(n) : "memory")

__device__ __forceinline__ void ldm4(uint32_t* r, uint32_t a) {
    asm volatile("ldmatrix.sync.aligned.m8n8.x4.shared.b16 {%0,%1,%2,%3}, [%4];"
                 : "=r"(r[0]), "=r"(r[1]), "=r"(r[2]), "=r"(r[3]) : "r"(a));
}
__device__ __forceinline__ void mma_f16(float* c, const uint32_t* a, const uint32_t* b) {
    asm volatile("mma.sync.aligned.m16n8k16.row.col.f32.f16.f16.f32 "
                 "{%0,%1,%2,%3}, {%4,%5,%6,%7}, {%8,%9}, {%0,%1,%2,%3};"
                 : "+f"(c[0]), "+f"(c[1]), "+f"(c[2]), "+f"(c[3])
                 : "r"(a[0]), "r"(a[1]), "r"(a[2]), "r"(a[3]), "r"(b[0]), "r"(b[1]));
}
// packed split: h = {lo=f16(a), hi=f16(b)}, l = packed residuals (6 SASS ops)
__device__ __forceinline__ void split2h(float a, float b, uint32_t& h, uint32_t& l) {
    asm("cvt.rn.f16x2.f32 %0, %1, %2;" : "=r"(h) : "f"(b), "f"(a));
    float fa, fb;
    asm("{ .reg .b16 x, y;\n mov.b32 {x, y}, %2;\n"
        " cvt.f32.f16 %0, x;\n cvt.f32.f16 %1, y; }"
        : "=f"(fa), "=f"(fb) : "r"(h));
    float ra = a - fa, rb = b - fb;
    asm("cvt.rn.f16x2.f32 %0, %1, %2;" : "=r"(l) : "f"(rb), "f"(ra));
}
__device__ __forceinline__ float ex2a(float x) {
    float r; asm("ex2.approx.f32 %0, %1;" : "=f"(r) : "f"(x)); return r;
}
#define C8 0.18033688011112042f   // 0.125 * log2(e)

// ---------------------------------------------------------------------------
// cvt kernels
// ---------------------------------------------------------------------------
__global__ __launch_bounds__(256) void cvt_act(const float* __restrict__ x,
                                               const float* __restrict__ c) {
    int i = blockIdx.x * 256 + threadIdx.x;       // per float4
    const int T = ROWS * CD / 4;
    const float* src; __half *dh, *dl; int j;
    if (i < T) { src = x; dh = g_xh; dl = g_xl; j = i; }
    else       { src = c; dh = g_ch; dl = g_cl; j = i - T; }
    float4 v = ((const float4*)src)[j];
    uint32_t h0, l0, h1, l1;
    split2h(v.x, v.y, h0, l0);
    split2h(v.z, v.w, h1, l1);
    ((uint2*)dh)[j] = make_uint2(h0, h1);
    ((uint2*)dl)[j] = make_uint2(l0, l1);
}

__global__ __launch_bounds__(256) void cvt_w(const float* __restrict__ Wq,
                                             const float* __restrict__ Wk,
                                             const float* __restrict__ Wv,
                                             const float* __restrict__ Wo) {
    int i = blockIdx.x * 256 + threadIdx.x;       // 4*512*512
    int w = i >> 18; int rem = i & 262143;
    int k = rem >> 9; int n = rem & 511;
    const float* W = (w == 0) ? Wq : (w == 1) ? Wk : (w == 2) ? Wv : Wo;
    ((uint16_t*)g_w[w])[n * CD + k] = __half_as_ushort(__float2half_rn(W[k * CD + n]));
}

// ---------------------------------------------------------------------------
// GEMM core: C[128x128] = A[128x512] (split) * B(nk)[128x512]^T (single).
// K-tile 64; stage: AH 0 (16K), AL 16K, B 32K; 2 stages (96KB total).
// 8 warps: wm=wid>>1 (4), wn=wid&1 (2); warp tile 32x64.
// ---------------------------------------------------------------------------
#define PJ_STG 49152

#define G_LOAD(Agh, Agl, Bg, s, kt) do {                                        \
    const int _k0 = (kt) * 64;                                                  \
    const uint32_t _bs = sb + (s) * PJ_STG;                                     \
    _Pragma("unroll")                                                           \
    for (int _t = 0; _t < 4; _t++) {                                            \
        int _ch = _t * 256 + tid;                                               \
        int _r = _ch >> 3, _c = _ch & 7;                                        \
        uint32_t _so = swz128((uint32_t)(_r * 128 + _c * 16));                  \
        size_t _ga = (size_t)(row0 + _r) * CD + _k0 + _c * 8;                   \
        size_t _gb = (size_t)(col0 + _r) * CD + _k0 + _c * 8;                   \
        cpa16(_bs + _so,         (Agh) + _ga);                                  \
        cpa16(_bs + 16384 + _so, (Agl) + _ga);                                  \
        cpa16(_bs + 32768 + _so, (Bg)  + _gb);                                  \
    }                                                                           \
} while (0)

#define G_COMPUTE(s) do {                                                       \
    const uint32_t _bs = sb + (s) * PJ_STG;                                     \
    _Pragma("unroll")                                                           \
    for (int ks = 0; ks < 4; ks++) {                                            \
        uint32_t ah[2][4], al[2][4];                                            \
        _Pragma("unroll")                                                       \
        for (int mf = 0; mf < 2; mf++) {                                        \
            uint32_t rel = swz128((uint32_t)((wm*32 + mf*16 + (lane & 15)) * 128 \
                                 + (lane >> 4) * 16 + ks * 32));                \
            ldm4(ah[mf], _bs + rel);                                            \
            ldm4(al[mf], _bs + 16384 + rel);                                    \
        }                                                                       \
        uint32_t bfr[8][2];                                                     \
        _Pragma("unroll")                                                       \
        for (int nt = 0; nt < 4; nt++) {                                        \
            uint32_t rel = swz128((uint32_t)((wn*64 + nt*16 + (lane & 15)) * 128 \
                                 + (lane >> 4) * 16 + ks * 32));                \
            uint32_t r[4];                                                      \
            ldm4(r, _bs + 32768 + rel);                                         \
            bfr[2*nt][0]=r[0]; bfr[2*nt][1]=r[2];                               \
            bfr[2*nt+1][0]=r[1]; bfr[2*nt+1][1]=r[3];                           \
        }                                                                       \
        _Pragma("unroll")                                                       \
        for (int mf = 0; mf < 2; mf++)                                          \
            _Pragma("unroll")                                                   \
            for (int nf = 0; nf < 8; nf++) {                                    \
                mma_f16(acc[mf][nf], ah[mf], bfr[nf]);                          \
                mma_f16(acc[mf][nf], al[mf], bfr[nf]);                          \
            }                                                                   \
    }                                                                           \
} while (0)

__global__ __launch_bounds__(256) void proj_mma() {
    extern __shared__ __align__(128) char smc[];
    const uint32_t sb = smem_u32(smc);
    const int tid = threadIdx.x, lane = tid & 31, wid = tid >> 5;
    const int wm = wid >> 1, wn = wid & 1;
    const int z = blockIdx.z;
    const int row0 = blockIdx.y * 128, col0 = blockIdx.x * 128;
    const __half* Agh = (z == 0) ? g_xh : g_ch;
    const __half* Agl = (z == 0) ? g_xl : g_cl;
    const __half* Bg  = g_w[z];

    float acc[2][8][4];
    #pragma unroll
    for (int i = 0; i < 2; i++)
        #pragma unroll
        for (int j = 0; j < 8; j++)
            #pragma unroll
            for (int k = 0; k < 4; k++) acc[i][j][k] = 0.f;

    G_LOAD(Agh, Agl, Bg, 0, 0); CP_COMMIT;
    for (int kt = 0; kt < 8; kt++) {
        if (kt < 7) { G_LOAD(Agh, Agl, Bg, (kt + 1) & 1, kt + 1); CP_COMMIT; CP_WAIT(1); }
        else CP_WAIT(0);
        __syncthreads();
        G_COMPUTE(kt & 1);
        __syncthreads();
    }

    #pragma unroll
    for (int mf = 0; mf < 2; mf++)
        #pragma unroll
        for (int nf = 0; nf < 8; nf++) {
            int rr = row0 + wm * 32 + mf * 16 + (lane >> 2);
            int cc = col0 + wn * 64 + nf * 8 + (lane & 3) * 2;
            #pragma unroll
            for (int hf = 0; hf < 2; hf++) {
                int R = rr + hf * 8;
                float v0 = acc[mf][nf][hf * 2 + 0];
                float v1 = acc[mf][nf][hf * 2 + 1];
                int b = R >> 11, n = R & 2047, hh = cc >> 6, d = cc & 63;
                if (z == 0) {            // Q: split, unscaled
                    uint32_t hv, lv; split2h(v0, v1, hv, lv);
                    size_t o = ((size_t)(b * HH + hh) * SEQ + n) * DH + d;
                    *(uint32_t*)(g_Qh + o) = hv;
                    *(uint32_t*)(g_Ql + o) = lv;
                } else if (z == 1) {     // K: single
                    uint32_t hv;
                    asm("cvt.rn.f16x2.f32 %0, %1, %2;" : "=r"(hv) : "f"(v1), "f"(v0));
                    size_t o = ((size_t)(b * HH + hh) * SEQ + n) * DH + d;
                    *(uint32_t*)(g_Kv + o) = hv;
                } else {                 // V: single, transposed [d][m]
                    size_t o = ((size_t)(b * HH + hh) * DH + d) * SEQ + n;
                    ((uint16_t*)g_Vv)[o]       = __half_as_ushort(__float2half_rn(v0));
                    ((uint16_t*)g_Vv)[o + SEQ] = __half_as_ushort(__float2half_rn(v1));
                }
            }
        }
}

__global__ __launch_bounds__(256) void out_mma(const float* __restrict__ bo,
                                               float* __restrict__ out) {
    extern __shared__ __align__(128) char smc[];
    const uint32_t sb = smem_u32(smc);
    const int tid = threadIdx.x, lane = tid & 31, wid = tid >> 5;
    const int wm = wid >> 1, wn = wid & 1;
    const int row0 = blockIdx.y * 128, col0 = blockIdx.x * 128;

    float acc[2][8][4];
    #pragma unroll
    for (int i = 0; i < 2; i++)
        #pragma unroll
        for (int j = 0; j < 8; j++)
            #pragma unroll
            for (int k = 0; k < 4; k++) acc[i][j][k] = 0.f;

    G_LOAD(g_Oh, g_Ol, g_w[3], 0, 0); CP_COMMIT;
    for (int kt = 0; kt < 8; kt++) {
        if (kt < 7) { G_LOAD(g_Oh, g_Ol, g_w[3], (kt + 1) & 1, kt + 1); CP_COMMIT; CP_WAIT(1); }
        else CP_WAIT(0);
        __syncthreads();
        G_COMPUTE(kt & 1);
        __syncthreads();
    }

    #pragma unroll
    for (int mf = 0; mf < 2; mf++)
        #pragma unroll
        for (int nf = 0; nf < 8; nf++) {
            int rr = row0 + wm * 32 + mf * 16 + (lane >> 2);
            int cc = col0 + wn * 64 + nf * 8 + (lane & 3) * 2;
            #pragma unroll
            for (int hf = 0; hf < 2; hf++) {
                int R = rr + hf * 8;
                float2 v;
                v.x = acc[mf][nf][hf * 2 + 0] * 0.015625f + __ldg(&bo[cc]);
                v.y = acc[mf][nf][hf * 2 + 1] * 0.015625f + __ldg(&bo[cc + 1]);
                *(float2*)(out + (size_t)R * CD + cc) = v;
            }
        }
}

// ---------------------------------------------------------------------------
// attention: 128 q/CTA; 16 stages of 128 keys, each computed as two 64-key
// halves (register footprint of the 64-key path). O in registers, unnormalized
// exp(s/8) via ex2. smem: QH 0 (16K), QL 16K; 2 stages at 32768 + s*32768:
// {K[128x64] 16K, V^T half0 [64x64] 8K, V^T half1 8K} = 96KB total.
// ---------------------------------------------------------------------------
#define AT_STG 32768

#define KV_LOAD(s, jj) do {                                                     \
    const int _m0 = (jj) * 128;                                                 \
    const uint32_t _bs = sb + 32768 + (s) * AT_STG;                             \
    _Pragma("unroll")                                                           \
    for (int _t = 0; _t < 4; _t++) {                                            \
        int _ch = _t * 256 + tid;                                               \
        {   int _r = _ch >> 3, _c = _ch & 7;                                    \
            uint32_t _so = swz128((uint32_t)(_r * 128 + _c * 16));              \
            size_t _gk = ((size_t)bh * SEQ + _m0 + _r) * DH + _c * 8;           \
            cpa16(_bs + _so, g_Kv + _gk);                                       \
        }                                                                       \
        {   int _d = _ch >> 4, _cc = _ch & 15;                                  \
            int _hf = _cc >> 3, _c = _cc & 7;                                   \
            uint32_t _so = 16384u + (uint32_t)_hf * 8192u                       \
                         + swz128((uint32_t)(_d * 128 + _c * 16));              \
            size_t _gv = ((size_t)bh * DH + _d) * SEQ + _m0 + _hf * 64 + _c * 8; \
            cpa16(_bs + _so, g_Vv + _gv);                                       \
        }                                                                       \
    }                                                                           \
} while (0)

__global__ __launch_bounds__(256, 2) void attn_mma() {
    extern __shared__ __align__(128) char smc[];
    const uint32_t sb = smem_u32(smc);
    const int tid = threadIdx.x, lane = tid & 31, wid = tid >> 5;
    const int q0 = blockIdx.x * 128, h = blockIdx.y, b = blockIdx.z;
    const int bh = b * HH + h;

    // Q tile (persistent, split): 1024 16B-chunks per array, 4/thread
    #pragma unroll
    for (int t = 0; t < 4; t++) {
        int ch = t * 256 + tid; int r = ch >> 3, c = ch & 7;
        uint32_t so = swz128((uint32_t)(r * 128 + c * 16));
        size_t g = ((size_t)bh * SEQ + q0 + r) * DH + c * 8;
        cpa16(sb + so,         g_Qh + g);
        cpa16(sb + 16384 + so, g_Ql + g);
    }
    KV_LOAD(0, 0); CP_COMMIT;

    float oacc[8][4];
    #pragma unroll
    for (int i = 0; i < 8; i++)
        #pragma unroll
        for (int k = 0; k < 4; k++) oacc[i][k] = 0.f;
    float l0 = 0.f, l1 = 0.f;

    for (int j = 0; j < 16; j++) {
        CP_WAIT(0);
        __syncthreads();
        if (j < 15) { KV_LOAD((j + 1) & 1, j + 1); CP_COMMIT; }
        const uint32_t st = sb + 32768 + (j & 1) * AT_STG;

        #pragma unroll
        for (int hf2 = 0; hf2 < 2; hf2++) {
            const uint32_t kb = st + (uint32_t)hf2 * 8192u;           // K rows hf2*64..
            const uint32_t vb = st + 16384u + (uint32_t)hf2 * 8192u;  // V^T half

            float sacc[8][4];
            #pragma unroll
            for (int i = 0; i < 8; i++)
                #pragma unroll
                for (int k = 0; k < 4; k++) sacc[i][k] = 0.f;

            // S = Q K^T  (A = Q split, B = K single)
            #pragma unroll
            for (int ks = 0; ks < 4; ks++) {
                uint32_t qh[4], ql[4];
                uint32_t relq = swz128((uint32_t)((wid * 16 + (lane & 15)) * 128
                                       + (lane >> 4) * 16 + ks * 32));
                ldm4(qh, sb + relq);
                ldm4(ql, sb + 16384 + relq);
                uint32_t kf[8][2];
                #pragma unroll
                for (int nt = 0; nt < 4; nt++) {
                    uint32_t rel = swz128((uint32_t)((nt * 16 + (lane & 15)) * 128
                                          + (lane >> 4) * 16 + ks * 32));
                    uint32_t r[4];
                    ldm4(r, kb + rel);
                    kf[2*nt][0]=r[0]; kf[2*nt][1]=r[2]; kf[2*nt+1][0]=r[1]; kf[2*nt+1][1]=r[3];
                }
                #pragma unroll
                for (int nf = 0; nf < 8; nf++) {
                    mma_f16(sacc[nf], qh, kf[nf]);
                    mma_f16(sacc[nf], ql, kf[nf]);
                }
            }

            // unnormalized exp(s/8) -> split P fragments (C layout == A layout)
            uint32_t pah[4][4], pal[4][4];
            #pragma unroll
            for (int kk = 0; kk < 4; kk++) {
                float e0 = ex2a(sacc[2*kk][0]   * C8), e1 = ex2a(sacc[2*kk][1]   * C8);
                float e2 = ex2a(sacc[2*kk][2]   * C8), e3 = ex2a(sacc[2*kk][3]   * C8);
                float e4 = ex2a(sacc[2*kk+1][0] * C8), e5 = ex2a(sacc[2*kk+1][1] * C8);
                float e6 = ex2a(sacc[2*kk+1][2] * C8), e7 = ex2a(sacc[2*kk+1][3] * C8);
                l0 += (e0 + e1) + (e4 + e5);
                l1 += (e2 + e3) + (e6 + e7);
                split2h(e0, e1, pah[kk][0], pal[kk][0]);
                split2h(e2, e3, pah[kk][1], pal[kk][1]);
                split2h(e4, e5, pah[kk][2], pal[kk][2]);
                split2h(e6, e7, pah[kk][3], pal[kk][3]);
            }

            // O += P V   (A = P split, B = V^T single [d][m])
            #pragma unroll
            for (int ks = 0; ks < 4; ks++) {
                uint32_t vf[8][2];
                #pragma unroll
                for (int nt = 0; nt < 4; nt++) {
                    uint32_t rel = swz128((uint32_t)((nt * 16 + (lane & 15)) * 128
                                          + (lane >> 4) * 16 + ks * 32));
                    uint32_t r[4];
                    ldm4(r, vb + rel);
                    vf[2*nt][0]=r[0]; vf[2*nt][1]=r[2]; vf[2*nt+1][0]=r[1]; vf[2*nt+1][1]=r[3];
                }
                #pragma unroll
                for (int nf = 0; nf < 8; nf++) {
                    mma_f16(oacc[nf], pah[ks], vf[nf]);
                    mma_f16(oacc[nf], pal[ks], vf[nf]);
                }
            }
        }
    }

    // row sums live on the lane-quad: reduce xor 1,2
    l0 += __shfl_xor_sync(0xffffffffu, l0, 1);
    l0 += __shfl_xor_sync(0xffffffffu, l0, 2);
    l1 += __shfl_xor_sync(0xffffffffu, l1, 1);
    l1 += __shfl_xor_sync(0xffffffffu, l1, 2);
    const float inv0 = 64.f / l0, inv1 = 64.f / l1;   // store O*64

    const int n0 = q0 + wid * 16 + (lane >> 2);
    #pragma unroll
    for (int nf = 0; nf < 8; nf++) {
        int d = nf * 8 + (lane & 3) * 2;
        int col = h * DH + d;
        uint32_t hv, lv;
        split2h(oacc[nf][0] * inv0, oacc[nf][1] * inv0, hv, lv);
        size_t o0 = ((size_t)b * SEQ + n0) * CD + col;
        *(uint32_t*)(g_Oh + o0) = hv; *(uint32_t*)(g_Ol + o0) = lv;
        split2h(oacc[nf][2] * inv1, oacc[nf][3] * inv1, hv, lv);
        size_t o1 = ((size_t)b * SEQ + n0 + 8) * CD + col;
        *(uint32_t*)(g_Oh + o1) = hv; *(uint32_t*)(g_Ol + o1) = lv;
    }
}

// ---------------------------------------------------------------------------
extern "C" void kernel_launch(void* const* d_in, const int* in_sizes, int n_in,
                              void* d_out, int out_size) {
    const float* x   = (const float*)d_in[0];
    const float* ctx = (const float*)d_in[1];
    const float* Wq  = (const float*)d_in[2];
    const float* Wk  = (const float*)d_in[3];
    const float* Wv  = (const float*)d_in[4];
    const float* Wo  = (const float*)d_in[5];
    const float* bo  = (const float*)d_in[6];
    float* out = (float*)d_out;

    static int inited = 0;
    if (!inited) {
        cudaFuncSetAttribute(proj_mma, cudaFuncAttributeMaxDynamicSharedMemorySize, 2 * PJ_STG);
        cudaFuncSetAttribute(out_mma,  cudaFuncAttributeMaxDynamicSharedMemorySize, 2 * PJ_STG);
        cudaFuncSetAttribute(attn_mma, cudaFuncAttributeMaxDynamicSharedMemorySize, 98304);
        inited = 1;
    }

    cvt_act<<<2 * ROWS * CD / 4 / 256, 256>>>(x, ctx);
    cvt_w<<<4 * CD * CD / 256, 256>>>(Wq, Wk, Wv, Wo);
    proj_mma<<<dim3(4, 64, 3), 256, 2 * PJ_STG>>>();
    attn_mma<<<dim3(SEQ / 128, HH, BB), 256, 98304>>>();
    out_mma<<<dim3(4, 64), 256, 2 * PJ_STG>>>(bo, out);
}

// round 9
// speedup vs baseline: 5.9452x; 1.1766x over previous
#include <cuda_runtime.h>
#include <cuda_fp16.h>
#include <stdint.h>

// ===========================================================================
// CrossAttention via mma.sync fp16 2-combo (A split hi/lo, B single), fp32 acc.
// R9: P carried as single fp16 in the PV MMA (residual combo dropped).
// B=4, N=M=2048, H=8, D=64, QUERY_DIM=INNER=512.
// ===========================================================================

#define BB   4
#define SEQ  2048
#define HH   8
#define DH   64
#define CD   512
#define ROWS 8192
#define BHD  (BB*HH*SEQ*DH)

__device__ __half g_xh[ROWS*CD], g_xl[ROWS*CD];
__device__ __half g_ch[ROWS*CD], g_cl[ROWS*CD];
__device__ __half g_w[4][CD*CD];                 // [n][k] transposed, single fp16
__device__ __half g_Qh[BHD], g_Ql[BHD];          // [bh][n][64] UNSCALED, split
__device__ __half g_Kv[BHD];                     // [bh][m][64] single
__device__ __half g_Vv[BHD];                     // [bh][d][m]  single, transposed
__device__ __half g_Oh[ROWS*CD], g_Ol[ROWS*CD];  // [row][512], O*64 split

// ---------------------------------------------------------------------------
__device__ __forceinline__ uint32_t smem_u32(const void* p) {
    uint32_t a;
    asm("{ .reg .u64 t; cvta.to.shared.u64 t, %1; cvt.u32.u64 %0, t; }"
        : "=r"(a) : "l"(p));
    return a;
}
__device__ __forceinline__ uint32_t swz128(uint32_t b) { return b ^ (((b >> 7) & 7u) << 4); }

__device__ __forceinline__ void cpa16(uint32_t d, const void* s) {
    asm volatile("cp.async.cg.shared.global [%0], [%1], 16;" :: "r"(d), "l"(s));
}
#define CP_COMMIT  asm volatile("cp.async.commit_group;" ::: "memory")
#define CP_WAIT(n) asm volatile("cp.async.wait_group %0;" :: "n"(n) : "memory")

__device__ __forceinline__ void ldm4(uint32_t* r, uint32_t a) {
    asm volatile("ldmatrix.sync.aligned.m8n8.x4.shared.b16 {%0,%1,%2,%3}, [%4];"
                 : "=r"(r[0]), "=r"(r[1]), "=r"(r[2]), "=r"(r[3]) : "r"(a));
}
__device__ __forceinline__ void mma_f16(float* c, const uint32_t* a, const uint32_t* b) {
    asm volatile("mma.sync.aligned.m16n8k16.row.col.f32.f16.f16.f32 "
                 "{%0,%1,%2,%3}, {%4,%5,%6,%7}, {%8,%9}, {%0,%1,%2,%3};"
                 : "+f"(c[0]), "+f"(c[1]), "+f"(c[2]), "+f"(c[3])
                 : "r"(a[0]), "r"(a[1]), "r"(a[2]), "r"(a[3]), "r"(b[0]), "r"(b[1]));
}
// packed split: h = {lo=f16(a), hi=f16(b)}, l = packed residuals (6 SASS ops)
__device__ __forceinline__ void split2h(float a, float b, uint32_t& h, uint32_t& l) {
    asm("cvt.rn.f16x2.f32 %0, %1, %2;" : "=r"(h) : "f"(b), "f"(a));
    float fa, fb;
    asm("{ .reg .b16 x, y;\n mov.b32 {x, y}, %2;\n"
        " cvt.f32.f16 %0, x;\n cvt.f32.f16 %1, y; }"
        : "=f"(fa), "=f"(fb) : "r"(h));
    float ra = a - fa, rb = b - fb;
    asm("cvt.rn.f16x2.f32 %0, %1, %2;" : "=r"(l) : "f"(rb), "f"(ra));
}
__device__ __forceinline__ uint32_t pack2h(float a, float b) {
    uint32_t h;
    asm("cvt.rn.f16x2.f32 %0, %1, %2;" : "=r"(h) : "f"(b), "f"(a));
    return h;
}
__device__ __forceinline__ float ex2a(float x) {
    float r; asm("ex2.approx.f32 %0, %1;" : "=f"(r) : "f"(x)); return r;
}
#define C8 0.18033688011112042f   // 0.125 * log2(e)

// ---------------------------------------------------------------------------
// cvt kernels
// ---------------------------------------------------------------------------
__global__ __launch_bounds__(256) void cvt_act(const float* __restrict__ x,
                                               const float* __restrict__ c) {
    int i = blockIdx.x * 256 + threadIdx.x;       // per float4
    const int T = ROWS * CD / 4;
    const float* src; __half *dh, *dl; int j;
    if (i < T) { src = x; dh = g_xh; dl = g_xl; j = i; }
    else       { src = c; dh = g_ch; dl = g_cl; j = i - T; }
    float4 v = ((const float4*)src)[j];
    uint32_t h0, l0, h1, l1;
    split2h(v.x, v.y, h0, l0);
    split2h(v.z, v.w, h1, l1);
    ((uint2*)dh)[j] = make_uint2(h0, h1);
    ((uint2*)dl)[j] = make_uint2(l0, l1);
}

__global__ __launch_bounds__(256) void cvt_w(const float* __restrict__ Wq,
                                             const float* __restrict__ Wk,
                                             const float* __restrict__ Wv,
                                             const float* __restrict__ Wo) {
    int i = blockIdx.x * 256 + threadIdx.x;       // 4*512*512
    int w = i >> 18; int rem = i & 262143;
    int k = rem >> 9; int n = rem & 511;
    const float* W = (w == 0) ? Wq : (w == 1) ? Wk : (w == 2) ? Wv : Wo;
    ((uint16_t*)g_w[w])[n * CD + k] = __half_as_ushort(__float2half_rn(W[k * CD + n]));
}

// ---------------------------------------------------------------------------
// GEMM core: C[128x128] = A[128x512] (split) * B(nk)[128x512]^T (single).
// K-tile 64; stage: AH 0 (16K), AL 16K, B 32K; 2 stages (96KB total).
// 8 warps: wm=wid>>1 (4), wn=wid&1 (2); warp tile 32x64.
// ---------------------------------------------------------------------------
#define PJ_STG 49152

#define G_LOAD(Agh, Agl, Bg, s, kt) do {                                        \
    const int _k0 = (kt) * 64;                                                  \
    const uint32_t _bs = sb + (s) * PJ_STG;                                     \
    _Pragma("unroll")                                                           \
    for (int _t = 0; _t < 4; _t++) {                                            \
        int _ch = _t * 256 + tid;                                               \
        int _r = _ch >> 3, _c = _ch & 7;                                        \
        uint32_t _so = swz128((uint32_t)(_r * 128 + _c * 16));                  \
        size_t _ga = (size_t)(row0 + _r) * CD + _k0 + _c * 8;                   \
        size_t _gb = (size_t)(col0 + _r) * CD + _k0 + _c * 8;                   \
        cpa16(_bs + _so,         (Agh) + _ga);                                  \
        cpa16(_bs + 16384 + _so, (Agl) + _ga);                                  \
        cpa16(_bs + 32768 + _so, (Bg)  + _gb);                                  \
    }                                                                           \
} while (0)

#define G_COMPUTE(s) do {                                                       \
    const uint32_t _bs = sb + (s) * PJ_STG;                                     \
    _Pragma("unroll")                                                           \
    for (int ks = 0; ks < 4; ks++) {                                            \
        uint32_t ah[2][4], al[2][4];                                            \
        _Pragma("unroll")                                                       \
        for (int mf = 0; mf < 2; mf++) {                                        \
            uint32_t rel = swz128((uint32_t)((wm*32 + mf*16 + (lane & 15)) * 128 \
                                 + (lane >> 4) * 16 + ks * 32));                \
            ldm4(ah[mf], _bs + rel);                                            \
            ldm4(al[mf], _bs + 16384 + rel);                                    \
        }                                                                       \
        uint32_t bfr[8][2];                                                     \
        _Pragma("unroll")                                                       \
        for (int nt = 0; nt < 4; nt++) {                                        \
            uint32_t rel = swz128((uint32_t)((wn*64 + nt*16 + (lane & 15)) * 128 \
                                 + (lane >> 4) * 16 + ks * 32));                \
            uint32_t r[4];                                                      \
            ldm4(r, _bs + 32768 + rel);                                         \
            bfr[2*nt][0]=r[0]; bfr[2*nt][1]=r[2];                               \
            bfr[2*nt+1][0]=r[1]; bfr[2*nt+1][1]=r[3];                           \
        }                                                                       \
        _Pragma("unroll")                                                       \
        for (int mf = 0; mf < 2; mf++)                                          \
            _Pragma("unroll")                                                   \
            for (int nf = 0; nf < 8; nf++) {                                    \
                mma_f16(acc[mf][nf], ah[mf], bfr[nf]);                          \
                mma_f16(acc[mf][nf], al[mf], bfr[nf]);                          \
            }                                                                   \
    }                                                                           \
} while (0)

__global__ __launch_bounds__(256) void proj_mma() {
    extern __shared__ __align__(128) char smc[];
    const uint32_t sb = smem_u32(smc);
    const int tid = threadIdx.x, lane = tid & 31, wid = tid >> 5;
    const int wm = wid >> 1, wn = wid & 1;
    const int z = blockIdx.z;
    const int row0 = blockIdx.y * 128, col0 = blockIdx.x * 128;
    const __half* Agh = (z == 0) ? g_xh : g_ch;
    const __half* Agl = (z == 0) ? g_xl : g_cl;
    const __half* Bg  = g_w[z];

    float acc[2][8][4];
    #pragma unroll
    for (int i = 0; i < 2; i++)
        #pragma unroll
        for (int j = 0; j < 8; j++)
            #pragma unroll
            for (int k = 0; k < 4; k++) acc[i][j][k] = 0.f;

    G_LOAD(Agh, Agl, Bg, 0, 0); CP_COMMIT;
    for (int kt = 0; kt < 8; kt++) {
        if (kt < 7) { G_LOAD(Agh, Agl, Bg, (kt + 1) & 1, kt + 1); CP_COMMIT; CP_WAIT(1); }
        else CP_WAIT(0);
        __syncthreads();
        G_COMPUTE(kt & 1);
        __syncthreads();
    }

    #pragma unroll
    for (int mf = 0; mf < 2; mf++)
        #pragma unroll
        for (int nf = 0; nf < 8; nf++) {
            int rr = row0 + wm * 32 + mf * 16 + (lane >> 2);
            int cc = col0 + wn * 64 + nf * 8 + (lane & 3) * 2;
            #pragma unroll
            for (int hf = 0; hf < 2; hf++) {
                int R = rr + hf * 8;
                float v0 = acc[mf][nf][hf * 2 + 0];
                float v1 = acc[mf][nf][hf * 2 + 1];
                int b = R >> 11, n = R & 2047, hh = cc >> 6, d = cc & 63;
                if (z == 0) {            // Q: split, unscaled
                    uint32_t hv, lv; split2h(v0, v1, hv, lv);
                    size_t o = ((size_t)(b * HH + hh) * SEQ + n) * DH + d;
                    *(uint32_t*)(g_Qh + o) = hv;
                    *(uint32_t*)(g_Ql + o) = lv;
                } else if (z == 1) {     // K: single
                    uint32_t hv = pack2h(v0, v1);
                    size_t o = ((size_t)(b * HH + hh) * SEQ + n) * DH + d;
                    *(uint32_t*)(g_Kv + o) = hv;
                } else {                 // V: single, transposed [d][m]
                    size_t o = ((size_t)(b * HH + hh) * DH + d) * SEQ + n;
                    ((uint16_t*)g_Vv)[o]       = __half_as_ushort(__float2half_rn(v0));
                    ((uint16_t*)g_Vv)[o + SEQ] = __half_as_ushort(__float2half_rn(v1));
                }
            }
        }
}

__global__ __launch_bounds__(256) void out_mma(const float* __restrict__ bo,
                                               float* __restrict__ out) {
    extern __shared__ __align__(128) char smc[];
    const uint32_t sb = smem_u32(smc);
    const int tid = threadIdx.x, lane = tid & 31, wid = tid >> 5;
    const int wm = wid >> 1, wn = wid & 1;
    const int row0 = blockIdx.y * 128, col0 = blockIdx.x * 128;

    float acc[2][8][4];
    #pragma unroll
    for (int i = 0; i < 2; i++)
        #pragma unroll
        for (int j = 0; j < 8; j++)
            #pragma unroll
            for (int k = 0; k < 4; k++) acc[i][j][k] = 0.f;

    G_LOAD(g_Oh, g_Ol, g_w[3], 0, 0); CP_COMMIT;
    for (int kt = 0; kt < 8; kt++) {
        if (kt < 7) { G_LOAD(g_Oh, g_Ol, g_w[3], (kt + 1) & 1, kt + 1); CP_COMMIT; CP_WAIT(1); }
        else CP_WAIT(0);
        __syncthreads();
        G_COMPUTE(kt & 1);
        __syncthreads();
    }

    #pragma unroll
    for (int mf = 0; mf < 2; mf++)
        #pragma unroll
        for (int nf = 0; nf < 8; nf++) {
            int rr = row0 + wm * 32 + mf * 16 + (lane >> 2);
            int cc = col0 + wn * 64 + nf * 8 + (lane & 3) * 2;
            #pragma unroll
            for (int hf = 0; hf < 2; hf++) {
                int R = rr + hf * 8;
                float2 v;
                v.x = acc[mf][nf][hf * 2 + 0] * 0.015625f + __ldg(&bo[cc]);
                v.y = acc[mf][nf][hf * 2 + 1] * 0.015625f + __ldg(&bo[cc + 1]);
                *(float2*)(out + (size_t)R * CD + cc) = v;
            }
        }
}

// ---------------------------------------------------------------------------
// attention: 128 q/CTA; 16 stages of 128 keys, each computed as two 64-key
// halves. O in registers, unnormalized exp(s/8) via ex2, P single fp16 in PV.
// smem: QH 0 (16K), QL 16K; 2 stages at 32768 + s*32768:
// {K[128x64] 16K, V^T half0 [64x64] 8K, V^T half1 8K} = 96KB total.
// ---------------------------------------------------------------------------
#define AT_STG 32768

#define KV_LOAD(s, jj) do {                                                     \
    const int _m0 = (jj) * 128;                                                 \
    const uint32_t _bs = sb + 32768 + (s) * AT_STG;                             \
    _Pragma("unroll")                                                           \
    for (int _t = 0; _t < 4; _t++) {                                            \
        int _ch = _t * 256 + tid;                                               \
        {   int _r = _ch >> 3, _c = _ch & 7;                                    \
            uint32_t _so = swz128((uint32_t)(_r * 128 + _c * 16));              \
            size_t _gk = ((size_t)bh * SEQ + _m0 + _r) * DH + _c * 8;           \
            cpa16(_bs + _so, g_Kv + _gk);                                       \
        }                                                                       \
        {   int _d = _ch >> 4, _cc = _ch & 15;                                  \
            int _hf = _cc >> 3, _c = _cc & 7;                                   \
            uint32_t _so = 16384u + (uint32_t)_hf * 8192u                       \
                         + swz128((uint32_t)(_d * 128 + _c * 16));              \
            size_t _gv = ((size_t)bh * DH + _d) * SEQ + _m0 + _hf * 64 + _c * 8; \
            cpa16(_bs + _so, g_Vv + _gv);                                       \
        }                                                                       \
    }                                                                           \
} while (0)

__global__ __launch_bounds__(256, 2) void attn_mma() {
    extern __shared__ __align__(128) char smc[];
    const uint32_t sb = smem_u32(smc);
    const int tid = threadIdx.x, lane = tid & 31, wid = tid >> 5;
    const int q0 = blockIdx.x * 128, h = blockIdx.y, b = blockIdx.z;
    const int bh = b * HH + h;

    // Q tile (persistent, split): 1024 16B-chunks per array, 4/thread
    #pragma unroll
    for (int t = 0; t < 4; t++) {
        int ch = t * 256 + tid; int r = ch >> 3, c = ch & 7;
        uint32_t so = swz128((uint32_t)(r * 128 + c * 16));
        size_t g = ((size_t)bh * SEQ + q0 + r) * DH + c * 8;
        cpa16(sb + so,         g_Qh + g);
        cpa16(sb + 16384 + so, g_Ql + g);
    }
    KV_LOAD(0, 0); CP_COMMIT;

    float oacc[8][4];
    #pragma unroll
    for (int i = 0; i < 8; i++)
        #pragma unroll
        for (int k = 0; k < 4; k++) oacc[i][k] = 0.f;
    float l0 = 0.f, l1 = 0.f;

    for (int j = 0; j < 16; j++) {
        CP_WAIT(0);
        __syncthreads();
        if (j < 15) { KV_LOAD((j + 1) & 1, j + 1); CP_COMMIT; }
        const uint32_t st = sb + 32768 + (j & 1) * AT_STG;

        #pragma unroll
        for (int hf2 = 0; hf2 < 2; hf2++) {
            const uint32_t kb = st + (uint32_t)hf2 * 8192u;           // K rows hf2*64..
            const uint32_t vb = st + 16384u + (uint32_t)hf2 * 8192u;  // V^T half

            float sacc[8][4];
            #pragma unroll
            for (int i = 0; i < 8; i++)
                #pragma unroll
                for (int k = 0; k < 4; k++) sacc[i][k] = 0.f;

            // S = Q K^T  (A = Q split, B = K single)
            #pragma unroll
            for (int ks = 0; ks < 4; ks++) {
                uint32_t qh[4], ql[4];
                uint32_t relq = swz128((uint32_t)((wid * 16 + (lane & 15)) * 128
                                       + (lane >> 4) * 16 + ks * 32));
                ldm4(qh, sb + relq);
                ldm4(ql, sb + 16384 + relq);
                uint32_t kf[8][2];
                #pragma unroll
                for (int nt = 0; nt < 4; nt++) {
                    uint32_t rel = swz128((uint32_t)((nt * 16 + (lane & 15)) * 128
                                          + (lane >> 4) * 16 + ks * 32));
                    uint32_t r[4];
                    ldm4(r, kb + rel);
                    kf[2*nt][0]=r[0]; kf[2*nt][1]=r[2]; kf[2*nt+1][0]=r[1]; kf[2*nt+1][1]=r[3];
                }
                #pragma unroll
                for (int nf = 0; nf < 8; nf++) {
                    mma_f16(sacc[nf], qh, kf[nf]);
                    mma_f16(sacc[nf], ql, kf[nf]);
                }
            }

            // unnormalized exp(s/8) -> single-fp16 P fragments (C layout == A layout)
            uint32_t pah[4][4];
            #pragma unroll
            for (int kk = 0; kk < 4; kk++) {
                float e0 = ex2a(sacc[2*kk][0]   * C8), e1 = ex2a(sacc[2*kk][1]   * C8);
                float e2 = ex2a(sacc[2*kk][2]   * C8), e3 = ex2a(sacc[2*kk][3]   * C8);
                float e4 = ex2a(sacc[2*kk+1][0] * C8), e5 = ex2a(sacc[2*kk+1][1] * C8);
                float e6 = ex2a(sacc[2*kk+1][2] * C8), e7 = ex2a(sacc[2*kk+1][3] * C8);
                l0 += (e0 + e1) + (e4 + e5);
                l1 += (e2 + e3) + (e6 + e7);
                pah[kk][0] = pack2h(e0, e1);
                pah[kk][1] = pack2h(e2, e3);
                pah[kk][2] = pack2h(e4, e5);
                pah[kk][3] = pack2h(e6, e7);
            }

            // O += P V   (A = P single fp16, B = V^T single [d][m])
            #pragma unroll
            for (int ks = 0; ks < 4; ks++) {
                uint32_t vf[8][2];
                #pragma unroll
                for (int nt = 0; nt < 4; nt++) {
                    uint32_t rel = swz128((uint32_t)((nt * 16 + (lane & 15)) * 128
                                          + (lane >> 4) * 16 + ks * 32));
                    uint32_t r[4];
                    ldm4(r, vb + rel);
                    vf[2*nt][0]=r[0]; vf[2*nt][1]=r[2]; vf[2*nt+1][0]=r[1]; vf[2*nt+1][1]=r[3];
                }
                #pragma unroll
                for (int nf = 0; nf < 8; nf++)
                    mma_f16(oacc[nf], pah[ks], vf[nf]);
            }
        }
    }

    // row sums live on the lane-quad: reduce xor 1,2
    l0 += __shfl_xor_sync(0xffffffffu, l0, 1);
    l0 += __shfl_xor_sync(0xffffffffu, l0, 2);
    l1 += __shfl_xor_sync(0xffffffffu, l1, 1);
    l1 += __shfl_xor_sync(0xffffffffu, l1, 2);
    const float inv0 = 64.f / l0, inv1 = 64.f / l1;   // store O*64

    const int n0 = q0 + wid * 16 + (lane >> 2);
    #pragma unroll
    for (int nf = 0; nf < 8; nf++) {
        int d = nf * 8 + (lane & 3) * 2;
        int col = h * DH + d;
        uint32_t hv, lv;
        split2h(oacc[nf][0] * inv0, oacc[nf][1] * inv0, hv, lv);
        size_t o0 = ((size_t)b * SEQ + n0) * CD + col;
        *(uint32_t*)(g_Oh + o0) = hv; *(uint32_t*)(g_Ol + o0) = lv;
        split2h(oacc[nf][2] * inv1, oacc[nf][3] * inv1, hv, lv);
        size_t o1 = ((size_t)b * SEQ + n0 + 8) * CD + col;
        *(uint32_t*)(g_Oh + o1) = hv; *(uint32_t*)(g_Ol + o1) = lv;
    }
}

// ---------------------------------------------------------------------------
extern "C" void kernel_launch(void* const* d_in, const int* in_sizes, int n_in,
                              void* d_out, int out_size) {
    const float* x   = (const float*)d_in[0];
    const float* ctx = (const float*)d_in[1];
    const float* Wq  = (const float*)d_in[2];
    const float* Wk  = (const float*)d_in[3];
    const float* Wv  = (const float*)d_in[4];
    const float* Wo  = (const float*)d_in[5];
    const float* bo  = (const float*)d_in[6];
    float* out = (float*)d_out;

    static int inited = 0;
    if (!inited) {
        cudaFuncSetAttribute(proj_mma, cudaFuncAttributeMaxDynamicSharedMemorySize, 2 * PJ_STG);
        cudaFuncSetAttribute(out_mma,  cudaFuncAttributeMaxDynamicSharedMemorySize, 2 * PJ_STG);
        cudaFuncSetAttribute(attn_mma, cudaFuncAttributeMaxDynamicSharedMemorySize, 98304);
        inited = 1;
    }

    cvt_act<<<2 * ROWS * CD / 4 / 256, 256>>>(x, ctx);
    cvt_w<<<4 * CD * CD / 256, 256>>>(Wq, Wk, Wv, Wo);
    proj_mma<<<dim3(4, 64, 3), 256, 2 * PJ_STG>>>();
    attn_mma<<<dim3(SEQ / 128, HH, BB), 256, 98304>>>();
    out_mma<<<dim3(4, 64), 256, 2 * PJ_STG>>>(bo, out);
}

// round 10
// speedup vs baseline: 7.3672x; 1.2392x over previous
#include <cuda_runtime.h>
#include <cuda_fp16.h>
#include <stdint.h>

// ===========================================================================
// CrossAttention via mma.sync fp16, fp32 accum.
// R10: exponent-folded operands (Q, K) carried single fp16; direct operands
// (activations->V, O) keep split hi/lo 2-combo.
// B=4, N=M=2048, H=8, D=64, QUERY_DIM=INNER=512.
// ===========================================================================

#define BB   4
#define SEQ  2048
#define HH   8
#define DH   64
#define CD   512
#define ROWS 8192
#define BHD  (BB*HH*SEQ*DH)

__device__ __half g_xh[ROWS*CD], g_xl[ROWS*CD];
__device__ __half g_ch[ROWS*CD], g_cl[ROWS*CD];
__device__ __half g_w[4][CD*CD];                 // [n][k] transposed, single fp16
__device__ __half g_Qv[BHD];                     // [bh][n][64] UNSCALED, single
__device__ __half g_Kv[BHD];                     // [bh][m][64] single
__device__ __half g_Vv[BHD];                     // [bh][d][m]  single, transposed
__device__ __half g_Oh[ROWS*CD], g_Ol[ROWS*CD];  // [row][512], O*64 split

// ---------------------------------------------------------------------------
__device__ __forceinline__ uint32_t smem_u32(const void* p) {
    uint32_t a;
    asm("{ .reg .u64 t; cvta.to.shared.u64 t, %1; cvt.u32.u64 %0, t; }"
        : "=r"(a) : "l"(p));
    return a;
}
__device__ __forceinline__ uint32_t swz128(uint32_t b) { return b ^ (((b >> 7) & 7u) << 4); }

__device__ __forceinline__ void cpa16(uint32_t d, const void* s) {
    asm volatile("cp.async.cg.shared.global [%0], [%1], 16;" :: "r"(d), "l"(s));
}
#define CP_COMMIT  asm volatile("cp.async.commit_group;" ::: "memory")
#define CP_WAIT(n) asm volatile("cp.async.wait_group %0;" :: "n"(n) : "memory")

__device__ __forceinline__ void ldm4(uint32_t* r, uint32_t a) {
    asm volatile("ldmatrix.sync.aligned.m8n8.x4.shared.b16 {%0,%1,%2,%3}, [%4];"
                 : "=r"(r[0]), "=r"(r[1]), "=r"(r[2]), "=r"(r[3]) : "r"(a));
}
__device__ __forceinline__ void mma_f16(float* c, const uint32_t* a, const uint32_t* b) {
    asm volatile("mma.sync.aligned.m16n8k16.row.col.f32.f16.f16.f32 "
                 "{%0,%1,%2,%3}, {%4,%5,%6,%7}, {%8,%9}, {%0,%1,%2,%3};"
                 : "+f"(c[0]), "+f"(c[1]), "+f"(c[2]), "+f"(c[3])
                 : "r"(a[0]), "r"(a[1]), "r"(a[2]), "r"(a[3]), "r"(b[0]), "r"(b[1]));
}
// packed split: h = {lo=f16(a), hi=f16(b)}, l = packed residuals (6 SASS ops)
__device__ __forceinline__ void split2h(float a, float b, uint32_t& h, uint32_t& l) {
    asm("cvt.rn.f16x2.f32 %0, %1, %2;" : "=r"(h) : "f"(b), "f"(a));
    float fa, fb;
    asm("{ .reg .b16 x, y;\n mov.b32 {x, y}, %2;\n"
        " cvt.f32.f16 %0, x;\n cvt.f32.f16 %1, y; }"
        : "=f"(fa), "=f"(fb) : "r"(h));
    float ra = a - fa, rb = b - fb;
    asm("cvt.rn.f16x2.f32 %0, %1, %2;" : "=r"(l) : "f"(rb), "f"(ra));
}
__device__ __forceinline__ uint32_t pack2h(float a, float b) {
    uint32_t h;
    asm("cvt.rn.f16x2.f32 %0, %1, %2;" : "=r"(h) : "f"(b), "f"(a));
    return h;
}
__device__ __forceinline__ float ex2a(float x) {
    float r; asm("ex2.approx.f32 %0, %1;" : "=f"(r) : "f"(x)); return r;
}
#define C8 0.18033688011112042f   // 0.125 * log2(e)

// ---------------------------------------------------------------------------
// cvt kernels
// ---------------------------------------------------------------------------
__global__ __launch_bounds__(256) void cvt_act(const float* __restrict__ x,
                                               const float* __restrict__ c) {
    int i = blockIdx.x * 256 + threadIdx.x;       // per float4
    const int T = ROWS * CD / 4;
    const float* src; __half *dh, *dl; int j;
    if (i < T) { src = x; dh = g_xh; dl = g_xl; j = i; }
    else       { src = c; dh = g_ch; dl = g_cl; j = i - T; }
    float4 v = ((const float4*)src)[j];
    uint32_t h0, l0, h1, l1;
    split2h(v.x, v.y, h0, l0);
    split2h(v.z, v.w, h1, l1);
    ((uint2*)dh)[j] = make_uint2(h0, h1);
    ((uint2*)dl)[j] = make_uint2(l0, l1);
}

__global__ __launch_bounds__(256) void cvt_w(const float* __restrict__ Wq,
                                             const float* __restrict__ Wk,
                                             const float* __restrict__ Wv,
                                             const float* __restrict__ Wo) {
    int i = blockIdx.x * 256 + threadIdx.x;       // 4*512*512
    int w = i >> 18; int rem = i & 262143;
    int k = rem >> 9; int n = rem & 511;
    const float* W = (w == 0) ? Wq : (w == 1) ? Wk : (w == 2) ? Wv : Wo;
    ((uint16_t*)g_w[w])[n * CD + k] = __half_as_ushort(__float2half_rn(W[k * CD + n]));
}

// ---------------------------------------------------------------------------
// GEMM core: C[128x128] = A[128x512] * B(nk)[128x512]^T (single fp16 B).
// A: split 2-combo when `asplit`, else single. K-tile 64.
// stage: AH 0 (16K), AL 16K, B 32K; 2 stages (96KB total).
// 8 warps: wm=wid>>1 (4), wn=wid&1 (2); warp tile 32x64.
// ---------------------------------------------------------------------------
#define PJ_STG 49152

#define G_LOAD(Agh, Agl, Bg, s, kt, asplit) do {                                \
    const int _k0 = (kt) * 64;                                                  \
    const uint32_t _bs = sb + (s) * PJ_STG;                                     \
    _Pragma("unroll")                                                           \
    for (int _t = 0; _t < 4; _t++) {                                            \
        int _ch = _t * 256 + tid;                                               \
        int _r = _ch >> 3, _c = _ch & 7;                                        \
        uint32_t _so = swz128((uint32_t)(_r * 128 + _c * 16));                  \
        size_t _ga = (size_t)(row0 + _r) * CD + _k0 + _c * 8;                   \
        size_t _gb = (size_t)(col0 + _r) * CD + _k0 + _c * 8;                   \
        cpa16(_bs + _so,         (Agh) + _ga);                                  \
        if (asplit) cpa16(_bs + 16384 + _so, (Agl) + _ga);                      \
        cpa16(_bs + 32768 + _so, (Bg)  + _gb);                                  \
    }                                                                           \
} while (0)

#define G_COMPUTE(s, asplit) do {                                               \
    const uint32_t _bs = sb + (s) * PJ_STG;                                     \
    _Pragma("unroll")                                                           \
    for (int ks = 0; ks < 4; ks++) {                                            \
        uint32_t ah[2][4], al[2][4];                                            \
        _Pragma("unroll")                                                       \
        for (int mf = 0; mf < 2; mf++) {                                        \
            uint32_t rel = swz128((uint32_t)((wm*32 + mf*16 + (lane & 15)) * 128 \
                                 + (lane >> 4) * 16 + ks * 32));                \
            ldm4(ah[mf], _bs + rel);                                            \
            if (asplit) ldm4(al[mf], _bs + 16384 + rel);                        \
        }                                                                       \
        uint32_t bfr[8][2];                                                     \
        _Pragma("unroll")                                                       \
        for (int nt = 0; nt < 4; nt++) {                                        \
            uint32_t rel = swz128((uint32_t)((wn*64 + nt*16 + (lane & 15)) * 128 \
                                 + (lane >> 4) * 16 + ks * 32));                \
            uint32_t r[4];                                                      \
            ldm4(r, _bs + 32768 + rel);                                         \
            bfr[2*nt][0]=r[0]; bfr[2*nt][1]=r[2];                               \
            bfr[2*nt+1][0]=r[1]; bfr[2*nt+1][1]=r[3];                           \
        }                                                                       \
        _Pragma("unroll")                                                       \
        for (int mf = 0; mf < 2; mf++)                                          \
            _Pragma("unroll")                                                   \
            for (int nf = 0; nf < 8; nf++) {                                    \
                mma_f16(acc[mf][nf], ah[mf], bfr[nf]);                          \
                if (asplit) mma_f16(acc[mf][nf], al[mf], bfr[nf]);              \
            }                                                                   \
    }                                                                           \
} while (0)

__global__ __launch_bounds__(256) void proj_mma() {
    extern __shared__ __align__(128) char smc[];
    const uint32_t sb = smem_u32(smc);
    const int tid = threadIdx.x, lane = tid & 31, wid = tid >> 5;
    const int wm = wid >> 1, wn = wid & 1;
    const int z = blockIdx.z;
    const int row0 = blockIdx.y * 128, col0 = blockIdx.x * 128;
    const __half* Agh = (z == 0) ? g_xh : g_ch;
    const __half* Agl = (z == 0) ? g_xl : g_cl;
    const __half* Bg  = g_w[z];
    const bool asplit = (z == 2);   // only V needs the residual combo

    float acc[2][8][4];
    #pragma unroll
    for (int i = 0; i < 2; i++)
        #pragma unroll
        for (int j = 0; j < 8; j++)
            #pragma unroll
            for (int k = 0; k < 4; k++) acc[i][j][k] = 0.f;

    G_LOAD(Agh, Agl, Bg, 0, 0, asplit); CP_COMMIT;
    for (int kt = 0; kt < 8; kt++) {
        if (kt < 7) { G_LOAD(Agh, Agl, Bg, (kt + 1) & 1, kt + 1, asplit); CP_COMMIT; CP_WAIT(1); }
        else CP_WAIT(0);
        __syncthreads();
        G_COMPUTE(kt & 1, asplit);
        __syncthreads();
    }

    #pragma unroll
    for (int mf = 0; mf < 2; mf++)
        #pragma unroll
        for (int nf = 0; nf < 8; nf++) {
            int rr = row0 + wm * 32 + mf * 16 + (lane >> 2);
            int cc = col0 + wn * 64 + nf * 8 + (lane & 3) * 2;
            #pragma unroll
            for (int hf = 0; hf < 2; hf++) {
                int R = rr + hf * 8;
                float v0 = acc[mf][nf][hf * 2 + 0];
                float v1 = acc[mf][nf][hf * 2 + 1];
                int b = R >> 11, n = R & 2047, hh = cc >> 6, d = cc & 63;
                if (z < 2) {             // Q or K: single fp16
                    __half* D = (z == 0) ? g_Qv : g_Kv;
                    size_t o = ((size_t)(b * HH + hh) * SEQ + n) * DH + d;
                    *(uint32_t*)(D + o) = pack2h(v0, v1);
                } else {                 // V: single, transposed [d][m]
                    size_t o = ((size_t)(b * HH + hh) * DH + d) * SEQ + n;
                    ((uint16_t*)g_Vv)[o]       = __half_as_ushort(__float2half_rn(v0));
                    ((uint16_t*)g_Vv)[o + SEQ] = __half_as_ushort(__float2half_rn(v1));
                }
            }
        }
}

__global__ __launch_bounds__(256) void out_mma(const float* __restrict__ bo,
                                               float* __restrict__ out) {
    extern __shared__ __align__(128) char smc[];
    const uint32_t sb = smem_u32(smc);
    const int tid = threadIdx.x, lane = tid & 31, wid = tid >> 5;
    const int wm = wid >> 1, wn = wid & 1;
    const int row0 = blockIdx.y * 128, col0 = blockIdx.x * 128;

    float acc[2][8][4];
    #pragma unroll
    for (int i = 0; i < 2; i++)
        #pragma unroll
        for (int j = 0; j < 8; j++)
            #pragma unroll
            for (int k = 0; k < 4; k++) acc[i][j][k] = 0.f;

    G_LOAD(g_Oh, g_Ol, g_w[3], 0, 0, true); CP_COMMIT;
    for (int kt = 0; kt < 8; kt++) {
        if (kt < 7) { G_LOAD(g_Oh, g_Ol, g_w[3], (kt + 1) & 1, kt + 1, true); CP_COMMIT; CP_WAIT(1); }
        else CP_WAIT(0);
        __syncthreads();
        G_COMPUTE(kt & 1, true);
        __syncthreads();
    }

    #pragma unroll
    for (int mf = 0; mf < 2; mf++)
        #pragma unroll
        for (int nf = 0; nf < 8; nf++) {
            int rr = row0 + wm * 32 + mf * 16 + (lane >> 2);
            int cc = col0 + wn * 64 + nf * 8 + (lane & 3) * 2;
            #pragma unroll
            for (int hf = 0; hf < 2; hf++) {
                int R = rr + hf * 8;
                float2 v;
                v.x = acc[mf][nf][hf * 2 + 0] * 0.015625f + __ldg(&bo[cc]);
                v.y = acc[mf][nf][hf * 2 + 1] * 0.015625f + __ldg(&bo[cc + 1]);
                *(float2*)(out + (size_t)R * CD + cc) = v;
            }
        }
}

// ---------------------------------------------------------------------------
// attention: 128 q/CTA; 16 stages of 128 keys, two 64-key halves each.
// Q single fp16 (exponent-folded), P single fp16, O in registers,
// unnormalized exp(s/8) via ex2.
// smem: Q 0 (16K); 2 stages at 16384 + s*32768: {K 16K, V0 8K, V1 8K} = 80KB.
// ---------------------------------------------------------------------------
#define AT_STG 32768

#define KV_LOAD(s, jj) do {                                                     \
    const int _m0 = (jj) * 128;                                                 \
    const uint32_t _bs = sb + 16384 + (s) * AT_STG;                             \
    _Pragma("unroll")                                                           \
    for (int _t = 0; _t < 4; _t++) {                                            \
        int _ch = _t * 256 + tid;                                               \
        {   int _r = _ch >> 3, _c = _ch & 7;                                    \
            uint32_t _so = swz128((uint32_t)(_r * 128 + _c * 16));              \
            size_t _gk = ((size_t)bh * SEQ + _m0 + _r) * DH + _c * 8;           \
            cpa16(_bs + _so, g_Kv + _gk);                                       \
        }                                                                       \
        {   int _d = _ch >> 4, _cc = _ch & 15;                                  \
            int _hf = _cc >> 3, _c = _cc & 7;                                   \
            uint32_t _so = 16384u + (uint32_t)_hf * 8192u                       \
                         + swz128((uint32_t)(_d * 128 + _c * 16));              \
            size_t _gv = ((size_t)bh * DH + _d) * SEQ + _m0 + _hf * 64 + _c * 8; \
            cpa16(_bs + _so, g_Vv + _gv);                                       \
        }                                                                       \
    }                                                                           \
} while (0)

__global__ __launch_bounds__(256, 2) void attn_mma() {
    extern __shared__ __align__(128) char smc[];
    const uint32_t sb = smem_u32(smc);
    const int tid = threadIdx.x, lane = tid & 31, wid = tid >> 5;
    const int q0 = blockIdx.x * 128, h = blockIdx.y, b = blockIdx.z;
    const int bh = b * HH + h;

    // Q tile (persistent, single): 1024 16B-chunks, 4/thread
    #pragma unroll
    for (int t = 0; t < 4; t++) {
        int ch = t * 256 + tid; int r = ch >> 3, c = ch & 7;
        uint32_t so = swz128((uint32_t)(r * 128 + c * 16));
        size_t g = ((size_t)bh * SEQ + q0 + r) * DH + c * 8;
        cpa16(sb + so, g_Qv + g);
    }
    KV_LOAD(0, 0); CP_COMMIT;

    float oacc[8][4];
    #pragma unroll
    for (int i = 0; i < 8; i++)
        #pragma unroll
        for (int k = 0; k < 4; k++) oacc[i][k] = 0.f;
    float l0 = 0.f, l1 = 0.f;

    for (int j = 0; j < 16; j++) {
        CP_WAIT(0);
        __syncthreads();
        if (j < 15) { KV_LOAD((j + 1) & 1, j + 1); CP_COMMIT; }
        const uint32_t st = sb + 16384 + (j & 1) * AT_STG;

        #pragma unroll
        for (int hf2 = 0; hf2 < 2; hf2++) {
            const uint32_t kb = st + (uint32_t)hf2 * 8192u;           // K rows hf2*64..
            const uint32_t vb = st + 16384u + (uint32_t)hf2 * 8192u;  // V^T half

            float sacc[8][4];
            #pragma unroll
            for (int i = 0; i < 8; i++)
                #pragma unroll
                for (int k = 0; k < 4; k++) sacc[i][k] = 0.f;

            // S = Q K^T  (A = Q single, B = K single)
            #pragma unroll
            for (int ks = 0; ks < 4; ks++) {
                uint32_t qh[4];
                uint32_t relq = swz128((uint32_t)((wid * 16 + (lane & 15)) * 128
                                       + (lane >> 4) * 16 + ks * 32));
                ldm4(qh, sb + relq);
                uint32_t kf[8][2];
                #pragma unroll
                for (int nt = 0; nt < 4; nt++) {
                    uint32_t rel = swz128((uint32_t)((nt * 16 + (lane & 15)) * 128
                                          + (lane >> 4) * 16 + ks * 32));
                    uint32_t r[4];
                    ldm4(r, kb + rel);
                    kf[2*nt][0]=r[0]; kf[2*nt][1]=r[2]; kf[2*nt+1][0]=r[1]; kf[2*nt+1][1]=r[3];
                }
                #pragma unroll
                for (int nf = 0; nf < 8; nf++)
                    mma_f16(sacc[nf], qh, kf[nf]);
            }

            // unnormalized exp(s/8) -> single-fp16 P fragments (C layout == A layout)
            uint32_t pah[4][4];
            #pragma unroll
            for (int kk = 0; kk < 4; kk++) {
                float e0 = ex2a(sacc[2*kk][0]   * C8), e1 = ex2a(sacc[2*kk][1]   * C8);
                float e2 = ex2a(sacc[2*kk][2]   * C8), e3 = ex2a(sacc[2*kk][3]   * C8);
                float e4 = ex2a(sacc[2*kk+1][0] * C8), e5 = ex2a(sacc[2*kk+1][1] * C8);
                float e6 = ex2a(sacc[2*kk+1][2] * C8), e7 = ex2a(sacc[2*kk+1][3] * C8);
                l0 += (e0 + e1) + (e4 + e5);
                l1 += (e2 + e3) + (e6 + e7);
                pah[kk][0] = pack2h(e0, e1);
                pah[kk][1] = pack2h(e2, e3);
                pah[kk][2] = pack2h(e4, e5);
                pah[kk][3] = pack2h(e6, e7);
            }

            // O += P V   (A = P single fp16, B = V^T single [d][m])
            #pragma unroll
            for (int ks = 0; ks < 4; ks++) {
                uint32_t vf[8][2];
                #pragma unroll
                for (int nt = 0; nt < 4; nt++) {
                    uint32_t rel = swz128((uint32_t)((nt * 16 + (lane & 15)) * 128
                                          + (lane >> 4) * 16 + ks * 32));
                    uint32_t r[4];
                    ldm4(r, vb + rel);
                    vf[2*nt][0]=r[0]; vf[2*nt][1]=r[2]; vf[2*nt+1][0]=r[1]; vf[2*nt+1][1]=r[3];
                }
                #pragma unroll
                for (int nf = 0; nf < 8; nf++)
                    mma_f16(oacc[nf], pah[ks], vf[nf]);
            }
        }
    }

    // row sums live on the lane-quad: reduce xor 1,2
    l0 += __shfl_xor_sync(0xffffffffu, l0, 1);
    l0 += __shfl_xor_sync(0xffffffffu, l0, 2);
    l1 += __shfl_xor_sync(0xffffffffu, l1, 1);
    l1 += __shfl_xor_sync(0xffffffffu, l1, 2);
    const float inv0 = 64.f / l0, inv1 = 64.f / l1;   // store O*64

    const int n0 = q0 + wid * 16 + (lane >> 2);
    #pragma unroll
    for (int nf = 0; nf < 8; nf++) {
        int d = nf * 8 + (lane & 3) * 2;
        int col = h * DH + d;
        uint32_t hv, lv;
        split2h(oacc[nf][0] * inv0, oacc[nf][1] * inv0, hv, lv);
        size_t o0 = ((size_t)b * SEQ + n0) * CD + col;
        *(uint32_t*)(g_Oh + o0) = hv; *(uint32_t*)(g_Ol + o0) = lv;
        split2h(oacc[nf][2] * inv1, oacc[nf][3] * inv1, hv, lv);
        size_t o1 = ((size_t)b * SEQ + n0 + 8) * CD + col;
        *(uint32_t*)(g_Oh + o1) = hv; *(uint32_t*)(g_Ol + o1) = lv;
    }
}

// ---------------------------------------------------------------------------
extern "C" void kernel_launch(void* const* d_in, const int* in_sizes, int n_in,
                              void* d_out, int out_size) {
    const float* x   = (const float*)d_in[0];
    const float* ctx = (const float*)d_in[1];
    const float* Wq  = (const float*)d_in[2];
    const float* Wk  = (const float*)d_in[3];
    const float* Wv  = (const float*)d_in[4];
    const float* Wo  = (const float*)d_in[5];
    const float* bo  = (const float*)d_in[6];
    float* out = (float*)d_out;

    static int inited = 0;
    if (!inited) {
        cudaFuncSetAttribute(proj_mma, cudaFuncAttributeMaxDynamicSharedMemorySize, 2 * PJ_STG);
        cudaFuncSetAttribute(out_mma,  cudaFuncAttributeMaxDynamicSharedMemorySize, 2 * PJ_STG);
        cudaFuncSetAttribute(attn_mma, cudaFuncAttributeMaxDynamicSharedMemorySize, 81920);
        inited = 1;
    }

    cvt_act<<<2 * ROWS * CD / 4 / 256, 256>>>(x, ctx);
    cvt_w<<<4 * CD * CD / 256, 256>>>(Wq, Wk, Wv, Wo);
    proj_mma<<<dim3(4, 64, 3), 256, 2 * PJ_STG>>>();
    attn_mma<<<dim3(SEQ / 128, HH, BB), 256, 81920>>>();
    out_mma<<<dim3(4, 64), 256, 2 * PJ_STG>>>(bo, out);
}

// round 11
// speedup vs baseline: 7.6605x; 1.0398x over previous
#include <cuda_runtime.h>
#include <cuda_fp16.h>
#include <stdint.h>

// ===========================================================================
// CrossAttention via mma.sync fp16, fp32 accum.
// R11: softmax via ex2.approx.f16x2; l accumulated with ones-B MMA (bias
// self-canceling in O/l); dead x-lo split removed.
// B=4, N=M=2048, H=8, D=64, QUERY_DIM=INNER=512.
// ===========================================================================

#define BB   4
#define SEQ  2048
#define HH   8
#define DH   64
#define CD   512
#define ROWS 8192
#define BHD  (BB*HH*SEQ*DH)

__device__ __half g_xh[ROWS*CD];                 // x hi only (Q proj is single-combo)
__device__ __half g_xl[ROWS*CD];                 // unused (kept for pointer plumbing)
__device__ __half g_ch[ROWS*CD], g_cl[ROWS*CD];
__device__ __half g_w[4][CD*CD];                 // [n][k] transposed, single fp16
__device__ __half g_Qv[BHD];                     // [bh][n][64] UNSCALED, single
__device__ __half g_Kv[BHD];                     // [bh][m][64] single
__device__ __half g_Vv[BHD];                     // [bh][d][m]  single, transposed
__device__ __half g_Oh[ROWS*CD], g_Ol[ROWS*CD];  // [row][512], O*64 split

// ---------------------------------------------------------------------------
__device__ __forceinline__ uint32_t smem_u32(const void* p) {
    uint32_t a;
    asm("{ .reg .u64 t; cvta.to.shared.u64 t, %1; cvt.u32.u64 %0, t; }"
        : "=r"(a) : "l"(p));
    return a;
}
__device__ __forceinline__ uint32_t swz128(uint32_t b) { return b ^ (((b >> 7) & 7u) << 4); }

__device__ __forceinline__ void cpa16(uint32_t d, const void* s) {
    asm volatile("cp.async.cg.shared.global [%0], [%1], 16;" :: "r"(d), "l"(s));
}
#define CP_COMMIT  asm volatile("cp.async.commit_group;" ::: "memory")
#define CP_WAIT(n) asm volatile("cp.async.wait_group %0;" :: "n"(n) : "memory")

__device__ __forceinline__ void ldm4(uint32_t* r, uint32_t a) {
    asm volatile("ldmatrix.sync.aligned.m8n8.x4.shared.b16 {%0,%1,%2,%3}, [%4];"
                 : "=r"(r[0]), "=r"(r[1]), "=r"(r[2]), "=r"(r[3]) : "r"(a));
}
__device__ __forceinline__ void mma_f16(float* c, const uint32_t* a, const uint32_t* b) {
    asm volatile("mma.sync.aligned.m16n8k16.row.col.f32.f16.f16.f32 "
                 "{%0,%1,%2,%3}, {%4,%5,%6,%7}, {%8,%9}, {%0,%1,%2,%3};"
                 : "+f"(c[0]), "+f"(c[1]), "+f"(c[2]), "+f"(c[3])
                 : "r"(a[0]), "r"(a[1]), "r"(a[2]), "r"(a[3]), "r"(b[0]), "r"(b[1]));
}
// packed split: h = {lo=f16(a), hi=f16(b)}, l = packed residuals (6 SASS ops)
__device__ __forceinline__ void split2h(float a, float b, uint32_t& h, uint32_t& l) {
    asm("cvt.rn.f16x2.f32 %0, %1, %2;" : "=r"(h) : "f"(b), "f"(a));
    float fa, fb;
    asm("{ .reg .b16 x, y;\n mov.b32 {x, y}, %2;\n"
        " cvt.f32.f16 %0, x;\n cvt.f32.f16 %1, y; }"
        : "=f"(fa), "=f"(fb) : "r"(h));
    float ra = a - fa, rb = b - fb;
    asm("cvt.rn.f16x2.f32 %0, %1, %2;" : "=r"(l) : "f"(rb), "f"(ra));
}
__device__ __forceinline__ uint32_t pack2h(float a, float b) {
    uint32_t h;
    asm("cvt.rn.f16x2.f32 %0, %1, %2;" : "=r"(h) : "f"(b), "f"(a));
    return h;
}
__device__ __forceinline__ uint32_t ex2h2(uint32_t x) {
    uint32_t r;
    asm("ex2.approx.f16x2 %0, %1;" : "=r"(r) : "r"(x));
    return r;
}
#define C8 0.18033688011112042f   // 0.125 * log2(e)
#define ONES_H2 0x3C003C00u       // (1.0h, 1.0h)

// ---------------------------------------------------------------------------
// cvt kernels
// ---------------------------------------------------------------------------
__global__ __launch_bounds__(256) void cvt_act(const float* __restrict__ x,
                                               const float* __restrict__ c) {
    int i = blockIdx.x * 256 + threadIdx.x;       // per float4
    const int T = ROWS * CD / 4;
    if (i < T) {                                  // x: hi only (lo never read)
        float4 v = ((const float4*)x)[i];
        ((uint2*)g_xh)[i] = make_uint2(pack2h(v.x, v.y), pack2h(v.z, v.w));
    } else {                                      // ctx: split hi/lo (V proj needs lo)
        int j = i - T;
        float4 v = ((const float4*)c)[j];
        uint32_t h0, l0, h1, l1;
        split2h(v.x, v.y, h0, l0);
        split2h(v.z, v.w, h1, l1);
        ((uint2*)g_ch)[j] = make_uint2(h0, h1);
        ((uint2*)g_cl)[j] = make_uint2(l0, l1);
    }
}

__global__ __launch_bounds__(256) void cvt_w(const float* __restrict__ Wq,
                                             const float* __restrict__ Wk,
                                             const float* __restrict__ Wv,
                                             const float* __restrict__ Wo) {
    int i = blockIdx.x * 256 + threadIdx.x;       // 4*512*512
    int w = i >> 18; int rem = i & 262143;
    int k = rem >> 9; int n = rem & 511;
    const float* W = (w == 0) ? Wq : (w == 1) ? Wk : (w == 2) ? Wv : Wo;
    ((uint16_t*)g_w[w])[n * CD + k] = __half_as_ushort(__float2half_rn(W[k * CD + n]));
}

// ---------------------------------------------------------------------------
// GEMM core: C[128x128] = A[128x512] * B(nk)[128x512]^T (single fp16 B).
// A: split 2-combo when `asplit`, else single. K-tile 64.
// stage: AH 0 (16K), AL 16K, B 32K; 2 stages (96KB total).
// 8 warps: wm=wid>>1 (4), wn=wid&1 (2); warp tile 32x64.
// ---------------------------------------------------------------------------
#define PJ_STG 49152

#define G_LOAD(Agh, Agl, Bg, s, kt, asplit) do {                                \
    const int _k0 = (kt) * 64;                                                  \
    const uint32_t _bs = sb + (s) * PJ_STG;                                     \
    _Pragma("unroll")                                                           \
    for (int _t = 0; _t < 4; _t++) {                                            \
        int _ch = _t * 256 + tid;                                               \
        int _r = _ch >> 3, _c = _ch & 7;                                        \
        uint32_t _so = swz128((uint32_t)(_r * 128 + _c * 16));                  \
        size_t _ga = (size_t)(row0 + _r) * CD + _k0 + _c * 8;                   \
        size_t _gb = (size_t)(col0 + _r) * CD + _k0 + _c * 8;                   \
        cpa16(_bs + _so,         (Agh) + _ga);                                  \
        if (asplit) cpa16(_bs + 16384 + _so, (Agl) + _ga);                      \
        cpa16(_bs + 32768 + _so, (Bg)  + _gb);                                  \
    }                                                                           \
} while (0)

#define G_COMPUTE(s, asplit) do {                                               \
    const uint32_t _bs = sb + (s) * PJ_STG;                                     \
    _Pragma("unroll")                                                           \
    for (int ks = 0; ks < 4; ks++) {                                            \
        uint32_t ah[2][4], al[2][4];                                            \
        _Pragma("unroll")                                                       \
        for (int mf = 0; mf < 2; mf++) {                                        \
            uint32_t rel = swz128((uint32_t)((wm*32 + mf*16 + (lane & 15)) * 128 \
                                 + (lane >> 4) * 16 + ks * 32));                \
            ldm4(ah[mf], _bs + rel);                                            \
            if (asplit) ldm4(al[mf], _bs + 16384 + rel);                        \
        }                                                                       \
        uint32_t bfr[8][2];                                                     \
        _Pragma("unroll")                                                       \
        for (int nt = 0; nt < 4; nt++) {                                        \
            uint32_t rel = swz128((uint32_t)((wn*64 + nt*16 + (lane & 15)) * 128 \
                                 + (lane >> 4) * 16 + ks * 32));                \
            uint32_t r[4];                                                      \
            ldm4(r, _bs + 32768 + rel);                                         \
            bfr[2*nt][0]=r[0]; bfr[2*nt][1]=r[2];                               \
            bfr[2*nt+1][0]=r[1]; bfr[2*nt+1][1]=r[3];                           \
        }                                                                       \
        _Pragma("unroll")                                                       \
        for (int mf = 0; mf < 2; mf++)                                          \
            _Pragma("unroll")                                                   \
            for (int nf = 0; nf < 8; nf++) {                                    \
                mma_f16(acc[mf][nf], ah[mf], bfr[nf]);                          \
                if (asplit) mma_f16(acc[mf][nf], al[mf], bfr[nf]);              \
            }                                                                   \
    }                                                                           \
} while (0)

__global__ __launch_bounds__(256) void proj_mma() {
    extern __shared__ __align__(128) char smc[];
    const uint32_t sb = smem_u32(smc);
    const int tid = threadIdx.x, lane = tid & 31, wid = tid >> 5;
    const int wm = wid >> 1, wn = wid & 1;
    const int z = blockIdx.z;
    const int row0 = blockIdx.y * 128, col0 = blockIdx.x * 128;
    const __half* Agh = (z == 0) ? g_xh : g_ch;
    const __half* Agl = (z == 0) ? g_xl : g_cl;
    const __half* Bg  = g_w[z];
    const bool asplit = (z == 2);   // only V needs the residual combo

    float acc[2][8][4];
    #pragma unroll
    for (int i = 0; i < 2; i++)
        #pragma unroll
        for (int j = 0; j < 8; j++)
            #pragma unroll
            for (int k = 0; k < 4; k++) acc[i][j][k] = 0.f;

    G_LOAD(Agh, Agl, Bg, 0, 0, asplit); CP_COMMIT;
    for (int kt = 0; kt < 8; kt++) {
        if (kt < 7) { G_LOAD(Agh, Agl, Bg, (kt + 1) & 1, kt + 1, asplit); CP_COMMIT; CP_WAIT(1); }
        else CP_WAIT(0);
        __syncthreads();
        G_COMPUTE(kt & 1, asplit);
        __syncthreads();
    }

    #pragma unroll
    for (int mf = 0; mf < 2; mf++)
        #pragma unroll
        for (int nf = 0; nf < 8; nf++) {
            int rr = row0 + wm * 32 + mf * 16 + (lane >> 2);
            int cc = col0 + wn * 64 + nf * 8 + (lane & 3) * 2;
            #pragma unroll
            for (int hf = 0; hf < 2; hf++) {
                int R = rr + hf * 8;
                float v0 = acc[mf][nf][hf * 2 + 0];
                float v1 = acc[mf][nf][hf * 2 + 1];
                int b = R >> 11, n = R & 2047, hh = cc >> 6, d = cc & 63;
                if (z < 2) {             // Q or K: single fp16
                    __half* D = (z == 0) ? g_Qv : g_Kv;
                    size_t o = ((size_t)(b * HH + hh) * SEQ + n) * DH + d;
                    *(uint32_t*)(D + o) = pack2h(v0, v1);
                } else {                 // V: single, transposed [d][m]
                    size_t o = ((size_t)(b * HH + hh) * DH + d) * SEQ + n;
                    ((uint16_t*)g_Vv)[o]       = __half_as_ushort(__float2half_rn(v0));
                    ((uint16_t*)g_Vv)[o + SEQ] = __half_as_ushort(__float2half_rn(v1));
                }
            }
        }
}

__global__ __launch_bounds__(256) void out_mma(const float* __restrict__ bo,
                                               float* __restrict__ out) {
    extern __shared__ __align__(128) char smc[];
    const uint32_t sb = smem_u32(smc);
    const int tid = threadIdx.x, lane = tid & 31, wid = tid >> 5;
    const int wm = wid >> 1, wn = wid & 1;
    const int row0 = blockIdx.y * 128, col0 = blockIdx.x * 128;

    float acc[2][8][4];
    #pragma unroll
    for (int i = 0; i < 2; i++)
        #pragma unroll
        for (int j = 0; j < 8; j++)
            #pragma unroll
            for (int k = 0; k < 4; k++) acc[i][j][k] = 0.f;

    G_LOAD(g_Oh, g_Ol, g_w[3], 0, 0, true); CP_COMMIT;
    for (int kt = 0; kt < 8; kt++) {
        if (kt < 7) { G_LOAD(g_Oh, g_Ol, g_w[3], (kt + 1) & 1, kt + 1, true); CP_COMMIT; CP_WAIT(1); }
        else CP_WAIT(0);
        __syncthreads();
        G_COMPUTE(kt & 1, true);
        __syncthreads();
    }

    #pragma unroll
    for (int mf = 0; mf < 2; mf++)
        #pragma unroll
        for (int nf = 0; nf < 8; nf++) {
            int rr = row0 + wm * 32 + mf * 16 + (lane >> 2);
            int cc = col0 + wn * 64 + nf * 8 + (lane & 3) * 2;
            #pragma unroll
            for (int hf = 0; hf < 2; hf++) {
                int R = rr + hf * 8;
                float2 v;
                v.x = acc[mf][nf][hf * 2 + 0] * 0.015625f + __ldg(&bo[cc]);
                v.y = acc[mf][nf][hf * 2 + 1] * 0.015625f + __ldg(&bo[cc + 1]);
                *(float2*)(out + (size_t)R * CD + cc) = v;
            }
        }
}

// ---------------------------------------------------------------------------
// attention: 128 q/CTA; 16 stages of 128 keys, two 64-key halves each.
// Q single fp16, P single fp16 via ex2.approx.f16x2, l via ones-B MMA
// (bias self-canceling in O/l), O in registers.
// smem: Q 0 (16K); 2 stages at 16384 + s*32768: {K 16K, V0 8K, V1 8K} = 80KB.
// ---------------------------------------------------------------------------
#define AT_STG 32768

#define KV_LOAD(s, jj) do {                                                     \
    const int _m0 = (jj) * 128;                                                 \
    const uint32_t _bs = sb + 16384 + (s) * AT_STG;                             \
    _Pragma("unroll")                                                           \
    for (int _t = 0; _t < 4; _t++) {                                            \
        int _ch = _t * 256 + tid;                                               \
        {   int _r = _ch >> 3, _c = _ch & 7;                                    \
            uint32_t _so = swz128((uint32_t)(_r * 128 + _c * 16));              \
            size_t _gk = ((size_t)bh * SEQ + _m0 + _r) * DH + _c * 8;           \
            cpa16(_bs + _so, g_Kv + _gk);                                       \
        }                                                                       \
        {   int _d = _ch >> 4, _cc = _ch & 15;                                  \
            int _hf = _cc >> 3, _c = _cc & 7;                                   \
            uint32_t _so = 16384u + (uint32_t)_hf * 8192u                       \
                         + swz128((uint32_t)(_d * 128 + _c * 16));              \
            size_t _gv = ((size_t)bh * DH + _d) * SEQ + _m0 + _hf * 64 + _c * 8; \
            cpa16(_bs + _so, g_Vv + _gv);                                       \
        }                                                                       \
    }                                                                           \
} while (0)

__global__ __launch_bounds__(256, 2) void attn_mma() {
    extern __shared__ __align__(128) char smc[];
    const uint32_t sb = smem_u32(smc);
    const int tid = threadIdx.x, lane = tid & 31, wid = tid >> 5;
    const int q0 = blockIdx.x * 128, h = blockIdx.y, b = blockIdx.z;
    const int bh = b * HH + h;

    // Q tile (persistent, single): 1024 16B-chunks, 4/thread
    #pragma unroll
    for (int t = 0; t < 4; t++) {
        int ch = t * 256 + tid; int r = ch >> 3, c = ch & 7;
        uint32_t so = swz128((uint32_t)(r * 128 + c * 16));
        size_t g = ((size_t)bh * SEQ + q0 + r) * DH + c * 8;
        cpa16(sb + so, g_Qv + g);
    }
    KV_LOAD(0, 0); CP_COMMIT;

    float oacc[8][4];
    #pragma unroll
    for (int i = 0; i < 8; i++)
        #pragma unroll
        for (int k = 0; k < 4; k++) oacc[i][k] = 0.f;
    float lacc[4] = {0.f, 0.f, 0.f, 0.f};   // row-sum accumulators via ones-MMA
    const uint32_t onesb[2] = {ONES_H2, ONES_H2};

    for (int j = 0; j < 16; j++) {
        CP_WAIT(0);
        __syncthreads();
        if (j < 15) { KV_LOAD((j + 1) & 1, j + 1); CP_COMMIT; }
        const uint32_t st = sb + 16384 + (j & 1) * AT_STG;

        #pragma unroll
        for (int hf2 = 0; hf2 < 2; hf2++) {
            const uint32_t kb = st + (uint32_t)hf2 * 8192u;           // K rows hf2*64..
            const uint32_t vb = st + 16384u + (uint32_t)hf2 * 8192u;  // V^T half

            float sacc[8][4];
            #pragma unroll
            for (int i = 0; i < 8; i++)
                #pragma unroll
                for (int k = 0; k < 4; k++) sacc[i][k] = 0.f;

            // S = Q K^T  (A = Q single, B = K single)
            #pragma unroll
            for (int ks = 0; ks < 4; ks++) {
                uint32_t qh[4];
                uint32_t relq = swz128((uint32_t)((wid * 16 + (lane & 15)) * 128
                                       + (lane >> 4) * 16 + ks * 32));
                ldm4(qh, sb + relq);
                uint32_t kf[8][2];
                #pragma unroll
                for (int nt = 0; nt < 4; nt++) {
                    uint32_t rel = swz128((uint32_t)((nt * 16 + (lane & 15)) * 128
                                          + (lane >> 4) * 16 + ks * 32));
                    uint32_t r[4];
                    ldm4(r, kb + rel);
                    kf[2*nt][0]=r[0]; kf[2*nt][1]=r[2]; kf[2*nt+1][0]=r[1]; kf[2*nt+1][1]=r[3];
                }
                #pragma unroll
                for (int nf = 0; nf < 8; nf++)
                    mma_f16(sacc[nf], qh, kf[nf]);
            }

            // P = ex2(s * 0.125*log2(e)) computed directly in packed fp16
            uint32_t pah[4][4];
            #pragma unroll
            for (int kk = 0; kk < 4; kk++) {
                pah[kk][0] = ex2h2(pack2h(sacc[2*kk][0]   * C8, sacc[2*kk][1]   * C8));
                pah[kk][1] = ex2h2(pack2h(sacc[2*kk][2]   * C8, sacc[2*kk][3]   * C8));
                pah[kk][2] = ex2h2(pack2h(sacc[2*kk+1][0] * C8, sacc[2*kk+1][1] * C8));
                pah[kk][3] = ex2h2(pack2h(sacc[2*kk+1][2] * C8, sacc[2*kk+1][3] * C8));
            }

            // l += P @ ones  (row sums on the tensor pipe, fp32 accum)
            #pragma unroll
            for (int ks = 0; ks < 4; ks++)
                mma_f16(lacc, pah[ks], onesb);

            // O += P V   (A = P single fp16, B = V^T single [d][m])
            #pragma unroll
            for (int ks = 0; ks < 4; ks++) {
                uint32_t vf[8][2];
                #pragma unroll
                for (int nt = 0; nt < 4; nt++) {
                    uint32_t rel = swz128((uint32_t)((nt * 16 + (lane & 15)) * 128
                                          + (lane >> 4) * 16 + ks * 32));
                    uint32_t r[4];
                    ldm4(r, vb + rel);
                    vf[2*nt][0]=r[0]; vf[2*nt][1]=r[2]; vf[2*nt+1][0]=r[1]; vf[2*nt+1][1]=r[3];
                }
                #pragma unroll
                for (int nf = 0; nf < 8; nf++)
                    mma_f16(oacc[nf], pah[ks], vf[nf]);
            }
        }
    }

    // lacc[0] / lacc[2] hold full row sums (ones-MMA summed over all keys)
    const float inv0 = 64.f / lacc[0], inv1 = 64.f / lacc[2];   // store O*64

    const int n0 = q0 + wid * 16 + (lane >> 2);
    #pragma unroll
    for (int nf = 0; nf < 8; nf++) {
        int d = nf * 8 + (lane & 3) * 2;
        int col = h * DH + d;
        uint32_t hv, lv;
        split2h(oacc[nf][0] * inv0, oacc[nf][1] * inv0, hv, lv);
        size_t o0 = ((size_t)b * SEQ + n0) * CD + col;
        *(uint32_t*)(g_Oh + o0) = hv; *(uint32_t*)(g_Ol + o0) = lv;
        split2h(oacc[nf][2] * inv1, oacc[nf][3] * inv1, hv, lv);
        size_t o1 = ((size_t)b * SEQ + n0 + 8) * CD + col;
        *(uint32_t*)(g_Oh + o1) = hv; *(uint32_t*)(g_Ol + o1) = lv;
    }
}

// ---------------------------------------------------------------------------
extern "C" void kernel_launch(void* const* d_in, const int* in_sizes, int n_in,
                              void* d_out, int out_size) {
    const float* x   = (const float*)d_in[0];
    const float* ctx = (const float*)d_in[1];
    const float* Wq  = (const float*)d_in[2];
    const float* Wk  = (const float*)d_in[3];
    const float* Wv  = (const float*)d_in[4];
    const float* Wo  = (const float*)d_in[5];
    const float* bo  = (const float*)d_in[6];
    float* out = (float*)d_out;

    static int inited = 0;
    if (!inited) {
        cudaFuncSetAttribute(proj_mma, cudaFuncAttributeMaxDynamicSharedMemorySize, 2 * PJ_STG);
        cudaFuncSetAttribute(out_mma,  cudaFuncAttributeMaxDynamicSharedMemorySize, 2 * PJ_STG);
        cudaFuncSetAttribute(attn_mma, cudaFuncAttributeMaxDynamicSharedMemorySize, 81920);
        inited = 1;
    }

    cvt_act<<<2 * ROWS * CD / 4 / 256, 256>>>(x, ctx);
    cvt_w<<<4 * CD * CD / 256, 256>>>(Wq, Wk, Wv, Wo);
    proj_mma<<<dim3(4, 64, 3), 256, 2 * PJ_STG>>>();
    attn_mma<<<dim3(SEQ / 128, HH, BB), 256, 81920>>>();
    out_mma<<<dim3(4, 64), 256, 2 * PJ_STG>>>(bo, out);
}

// round 12
// speedup vs baseline: 7.8744x; 1.0279x over previous
#include <cuda_runtime.h>
#include <cuda_fp16.h>
#include <stdint.h>

// ===========================================================================
// CrossAttention via mma.sync fp16, fp32 accum.
// R12: attn q-tile 256/CTA (warp = 32 q rows) -> K/V ldsm amortized over 2
// m-frags; 1 CTA/SM. Numerics identical to R11.
// B=4, N=M=2048, H=8, D=64, QUERY_DIM=INNER=512.
// ===========================================================================

#define BB   4
#define SEQ  2048
#define HH   8
#define DH   64
#define CD   512
#define ROWS 8192
#define BHD  (BB*HH*SEQ*DH)

__device__ __half g_xh[ROWS*CD];                 // x hi only (Q proj is single-combo)
__device__ __half g_xl[ROWS*CD];                 // unused (pointer plumbing)
__device__ __half g_ch[ROWS*CD], g_cl[ROWS*CD];
__device__ __half g_w[4][CD*CD];                 // [n][k] transposed, single fp16
__device__ __half g_Qv[BHD];                     // [bh][n][64] UNSCALED, single
__device__ __half g_Kv[BHD];                     // [bh][m][64] single
__device__ __half g_Vv[BHD];                     // [bh][d][m]  single, transposed
__device__ __half g_Oh[ROWS*CD], g_Ol[ROWS*CD];  // [row][512], O*64 split

// ---------------------------------------------------------------------------
__device__ __forceinline__ uint32_t smem_u32(const void* p) {
    uint32_t a;
    asm("{ .reg .u64 t; cvta.to.shared.u64 t, %1; cvt.u32.u64 %0, t; }"
        : "=r"(a) : "l"(p));
    return a;
}
__device__ __forceinline__ uint32_t swz128(uint32_t b) { return b ^ (((b >> 7) & 7u) << 4); }

__device__ __forceinline__ void cpa16(uint32_t d, const void* s) {
    asm volatile("cp.async.cg.shared.global [%0], [%1], 16;" :: "r"(d), "l"(s));
}
#define CP_COMMIT  asm volatile("cp.async.commit_group;" ::: "memory")
#define CP_WAIT(n) asm volatile("cp.async.wait_group %0;" :: "n"(n) : "memory")

__device__ __forceinline__ void ldm4(uint32_t* r, uint32_t a) {
    asm volatile("ldmatrix.sync.aligned.m8n8.x4.shared.b16 {%0,%1,%2,%3}, [%4];"
                 : "=r"(r[0]), "=r"(r[1]), "=r"(r[2]), "=r"(r[3]) : "r"(a));
}
__device__ __forceinline__ void mma_f16(float* c, const uint32_t* a, const uint32_t* b) {
    asm volatile("mma.sync.aligned.m16n8k16.row.col.f32.f16.f16.f32 "
                 "{%0,%1,%2,%3}, {%4,%5,%6,%7}, {%8,%9}, {%0,%1,%2,%3};"
                 : "+f"(c[0]), "+f"(c[1]), "+f"(c[2]), "+f"(c[3])
                 : "r"(a[0]), "r"(a[1]), "r"(a[2]), "r"(a[3]), "r"(b[0]), "r"(b[1]));
}
// packed split: h = {lo=f16(a), hi=f16(b)}, l = packed residuals (6 SASS ops)
__device__ __forceinline__ void split2h(float a, float b, uint32_t& h, uint32_t& l) {
    asm("cvt.rn.f16x2.f32 %0, %1, %2;" : "=r"(h) : "f"(b), "f"(a));
    float fa, fb;
    asm("{ .reg .b16 x, y;\n mov.b32 {x, y}, %2;\n"
        " cvt.f32.f16 %0, x;\n cvt.f32.f16 %1, y; }"
        : "=f"(fa), "=f"(fb) : "r"(h));
    float ra = a - fa, rb = b - fb;
    asm("cvt.rn.f16x2.f32 %0, %1, %2;" : "=r"(l) : "f"(rb), "f"(ra));
}
__device__ __forceinline__ uint32_t pack2h(float a, float b) {
    uint32_t h;
    asm("cvt.rn.f16x2.f32 %0, %1, %2;" : "=r"(h) : "f"(b), "f"(a));
    return h;
}
__device__ __forceinline__ uint32_t ex2h2(uint32_t x) {
    uint32_t r;
    asm("ex2.approx.f16x2 %0, %1;" : "=r"(r) : "r"(x));
    return r;
}
#define C8 0.18033688011112042f   // 0.125 * log2(e)
#define ONES_H2 0x3C003C00u       // (1.0h, 1.0h)

// ---------------------------------------------------------------------------
// cvt kernels
// ---------------------------------------------------------------------------
__global__ __launch_bounds__(256) void cvt_act(const float* __restrict__ x,
                                               const float* __restrict__ c) {
    int i = blockIdx.x * 256 + threadIdx.x;       // per float4
    const int T = ROWS * CD / 4;
    if (i < T) {                                  // x: hi only (lo never read)
        float4 v = ((const float4*)x)[i];
        ((uint2*)g_xh)[i] = make_uint2(pack2h(v.x, v.y), pack2h(v.z, v.w));
    } else {                                      // ctx: split hi/lo (V proj needs lo)
        int j = i - T;
        float4 v = ((const float4*)c)[j];
        uint32_t h0, l0, h1, l1;
        split2h(v.x, v.y, h0, l0);
        split2h(v.z, v.w, h1, l1);
        ((uint2*)g_ch)[j] = make_uint2(h0, h1);
        ((uint2*)g_cl)[j] = make_uint2(l0, l1);
    }
}

__global__ __launch_bounds__(256) void cvt_w(const float* __restrict__ Wq,
                                             const float* __restrict__ Wk,
                                             const float* __restrict__ Wv,
                                             const float* __restrict__ Wo) {
    int i = blockIdx.x * 256 + threadIdx.x;       // 4*512*512
    int w = i >> 18; int rem = i & 262143;
    int k = rem >> 9; int n = rem & 511;
    const float* W = (w == 0) ? Wq : (w == 1) ? Wk : (w == 2) ? Wv : Wo;
    ((uint16_t*)g_w[w])[n * CD + k] = __half_as_ushort(__float2half_rn(W[k * CD + n]));
}

// ---------------------------------------------------------------------------
// GEMM core (unchanged from R11): C[128x128] = A * B(nk)^T, B single fp16.
// ---------------------------------------------------------------------------
#define PJ_STG 49152

#define G_LOAD(Agh, Agl, Bg, s, kt, asplit) do {                                \
    const int _k0 = (kt) * 64;                                                  \
    const uint32_t _bs = sb + (s) * PJ_STG;                                     \
    _Pragma("unroll")                                                           \
    for (int _t = 0; _t < 4; _t++) {                                            \
        int _ch = _t * 256 + tid;                                               \
        int _r = _ch >> 3, _c = _ch & 7;                                        \
        uint32_t _so = swz128((uint32_t)(_r * 128 + _c * 16));                  \
        size_t _ga = (size_t)(row0 + _r) * CD + _k0 + _c * 8;                   \
        size_t _gb = (size_t)(col0 + _r) * CD + _k0 + _c * 8;                   \
        cpa16(_bs + _so,         (Agh) + _ga);                                  \
        if (asplit) cpa16(_bs + 16384 + _so, (Agl) + _ga);                      \
        cpa16(_bs + 32768 + _so, (Bg)  + _gb);                                  \
    }                                                                           \
} while (0)

#define G_COMPUTE(s, asplit) do {                                               \
    const uint32_t _bs = sb + (s) * PJ_STG;                                     \
    _Pragma("unroll")                                                           \
    for (int ks = 0; ks < 4; ks++) {                                            \
        uint32_t ah[2][4], al[2][4];                                            \
        _Pragma("unroll")                                                       \
        for (int mf = 0; mf < 2; mf++) {                                        \
            uint32_t rel = swz128((uint32_t)((wm*32 + mf*16 + (lane & 15)) * 128 \
                                 + (lane >> 4) * 16 + ks * 32));                \
            ldm4(ah[mf], _bs + rel);                                            \
            if (asplit) ldm4(al[mf], _bs + 16384 + rel);                        \
        }                                                                       \
        uint32_t bfr[8][2];                                                     \
        _Pragma("unroll")                                                       \
        for (int nt = 0; nt < 4; nt++) {                                        \
            uint32_t rel = swz128((uint32_t)((wn*64 + nt*16 + (lane & 15)) * 128 \
                                 + (lane >> 4) * 16 + ks * 32));                \
            uint32_t r[4];                                                      \
            ldm4(r, _bs + 32768 + rel);                                         \
            bfr[2*nt][0]=r[0]; bfr[2*nt][1]=r[2];                               \
            bfr[2*nt+1][0]=r[1]; bfr[2*nt+1][1]=r[3];                           \
        }                                                                       \
        _Pragma("unroll")                                                       \
        for (int mf = 0; mf < 2; mf++)                                          \
            _Pragma("unroll")                                                   \
            for (int nf = 0; nf < 8; nf++) {                                    \
                mma_f16(acc[mf][nf], ah[mf], bfr[nf]);                          \
                if (asplit) mma_f16(acc[mf][nf], al[mf], bfr[nf]);              \
            }                                                                   \
    }                                                                           \
} while (0)

__global__ __launch_bounds__(256) void proj_mma() {
    extern __shared__ __align__(128) char smc[];
    const uint32_t sb = smem_u32(smc);
    const int tid = threadIdx.x, lane = tid & 31, wid = tid >> 5;
    const int wm = wid >> 1, wn = wid & 1;
    const int z = blockIdx.z;
    const int row0 = blockIdx.y * 128, col0 = blockIdx.x * 128;
    const __half* Agh = (z == 0) ? g_xh : g_ch;
    const __half* Agl = (z == 0) ? g_xl : g_cl;
    const __half* Bg  = g_w[z];
    const bool asplit = (z == 2);   // only V needs the residual combo

    float acc[2][8][4];
    #pragma unroll
    for (int i = 0; i < 2; i++)
        #pragma unroll
        for (int j = 0; j < 8; j++)
            #pragma unroll
            for (int k = 0; k < 4; k++) acc[i][j][k] = 0.f;

    G_LOAD(Agh, Agl, Bg, 0, 0, asplit); CP_COMMIT;
    for (int kt = 0; kt < 8; kt++) {
        if (kt < 7) { G_LOAD(Agh, Agl, Bg, (kt + 1) & 1, kt + 1, asplit); CP_COMMIT; CP_WAIT(1); }
        else CP_WAIT(0);
        __syncthreads();
        G_COMPUTE(kt & 1, asplit);
        __syncthreads();
    }

    #pragma unroll
    for (int mf = 0; mf < 2; mf++)
        #pragma unroll
        for (int nf = 0; nf < 8; nf++) {
            int rr = row0 + wm * 32 + mf * 16 + (lane >> 2);
            int cc = col0 + wn * 64 + nf * 8 + (lane & 3) * 2;
            #pragma unroll
            for (int hf = 0; hf < 2; hf++) {
                int R = rr + hf * 8;
                float v0 = acc[mf][nf][hf * 2 + 0];
                float v1 = acc[mf][nf][hf * 2 + 1];
                int b = R >> 11, n = R & 2047, hh = cc >> 6, d = cc & 63;
                if (z < 2) {             // Q or K: single fp16
                    __half* D = (z == 0) ? g_Qv : g_Kv;
                    size_t o = ((size_t)(b * HH + hh) * SEQ + n) * DH + d;
                    *(uint32_t*)(D + o) = pack2h(v0, v1);
                } else {                 // V: single, transposed [d][m]
                    size_t o = ((size_t)(b * HH + hh) * DH + d) * SEQ + n;
                    ((uint16_t*)g_Vv)[o]       = __half_as_ushort(__float2half_rn(v0));
                    ((uint16_t*)g_Vv)[o + SEQ] = __half_as_ushort(__float2half_rn(v1));
                }
            }
        }
}

__global__ __launch_bounds__(256) void out_mma(const float* __restrict__ bo,
                                               float* __restrict__ out) {
    extern __shared__ __align__(128) char smc[];
    const uint32_t sb = smem_u32(smc);
    const int tid = threadIdx.x, lane = tid & 31, wid = tid >> 5;
    const int wm = wid >> 1, wn = wid & 1;
    const int row0 = blockIdx.y * 128, col0 = blockIdx.x * 128;

    float acc[2][8][4];
    #pragma unroll
    for (int i = 0; i < 2; i++)
        #pragma unroll
        for (int j = 0; j < 8; j++)
            #pragma unroll
            for (int k = 0; k < 4; k++) acc[i][j][k] = 0.f;

    G_LOAD(g_Oh, g_Ol, g_w[3], 0, 0, true); CP_COMMIT;
    for (int kt = 0; kt < 8; kt++) {
        if (kt < 7) { G_LOAD(g_Oh, g_Ol, g_w[3], (kt + 1) & 1, kt + 1, true); CP_COMMIT; CP_WAIT(1); }
        else CP_WAIT(0);
        __syncthreads();
        G_COMPUTE(kt & 1, true);
        __syncthreads();
    }

    #pragma unroll
    for (int mf = 0; mf < 2; mf++)
        #pragma unroll
        for (int nf = 0; nf < 8; nf++) {
            int rr = row0 + wm * 32 + mf * 16 + (lane >> 2);
            int cc = col0 + wn * 64 + nf * 8 + (lane & 3) * 2;
            #pragma unroll
            for (int hf = 0; hf < 2; hf++) {
                int R = rr + hf * 8;
                float2 v;
                v.x = acc[mf][nf][hf * 2 + 0] * 0.015625f + __ldg(&bo[cc]);
                v.y = acc[mf][nf][hf * 2 + 1] * 0.015625f + __ldg(&bo[cc + 1]);
                *(float2*)(out + (size_t)R * CD + cc) = v;
            }
        }
}

// ---------------------------------------------------------------------------
// attention: 256 q/CTA (warp = 32 q rows via 2 m-frags); 16 stages of 128
// keys, two 64-key halves. K/V fragments loaded once per warp and reused
// across both m-frags. Q single, P single via ex2.f16x2, l via ones-MMA.
// smem: Q 0 (32K); 2 stages at 32768 + s*32768: {K 16K, V0 8K, V1 8K} = 96KB.
// ---------------------------------------------------------------------------
#define AT_STG 32768

#define KV_LOAD(s, jj) do {                                                     \
    const int _m0 = (jj) * 128;                                                 \
    const uint32_t _bs = sb + 32768 + (s) * AT_STG;                             \
    _Pragma("unroll")                                                           \
    for (int _t = 0; _t < 4; _t++) {                                            \
        int _ch = _t * 256 + tid;                                               \
        {   int _r = _ch >> 3, _c = _ch & 7;                                    \
            uint32_t _so = swz128((uint32_t)(_r * 128 + _c * 16));              \
            size_t _gk = ((size_t)bh * SEQ + _m0 + _r) * DH + _c * 8;           \
            cpa16(_bs + _so, g_Kv + _gk);                                       \
        }                                                                       \
        {   int _d = _ch >> 4, _cc = _ch & 15;                                  \
            int _hf = _cc >> 3, _c = _cc & 7;                                   \
            uint32_t _so = 16384u + (uint32_t)_hf * 8192u                       \
                         + swz128((uint32_t)(_d * 128 + _c * 16));              \
            size_t _gv = ((size_t)bh * DH + _d) * SEQ + _m0 + _hf * 64 + _c * 8; \
            cpa16(_bs + _so, g_Vv + _gv);                                       \
        }                                                                       \
    }                                                                           \
} while (0)

__global__ __launch_bounds__(256, 1) void attn_mma() {
    extern __shared__ __align__(128) char smc[];
    const uint32_t sb = smem_u32(smc);
    const int tid = threadIdx.x, lane = tid & 31, wid = tid >> 5;
    const int q0 = blockIdx.x * 256, h = blockIdx.y, b = blockIdx.z;
    const int bh = b * HH + h;

    // Q tile (persistent, single): 256 rows x 128B = 2048 16B-chunks, 8/thread
    #pragma unroll
    for (int t = 0; t < 8; t++) {
        int ch = t * 256 + tid; int r = ch >> 3, c = ch & 7;
        uint32_t so = swz128((uint32_t)(r * 128 + c * 16));
        size_t g = ((size_t)bh * SEQ + q0 + r) * DH + c * 8;
        cpa16(sb + so, g_Qv + g);
    }
    KV_LOAD(0, 0); CP_COMMIT;

    float oacc[2][8][4];
    #pragma unroll
    for (int m = 0; m < 2; m++)
        #pragma unroll
        for (int i = 0; i < 8; i++)
            #pragma unroll
            for (int k = 0; k < 4; k++) oacc[m][i][k] = 0.f;
    float lacc[2][4] = {{0.f,0.f,0.f,0.f},{0.f,0.f,0.f,0.f}};
    const uint32_t onesb[2] = {ONES_H2, ONES_H2};

    for (int j = 0; j < 16; j++) {
        CP_WAIT(0);
        __syncthreads();
        if (j < 15) { KV_LOAD((j + 1) & 1, j + 1); CP_COMMIT; }
        const uint32_t st = sb + 32768 + (j & 1) * AT_STG;

        #pragma unroll
        for (int hf2 = 0; hf2 < 2; hf2++) {
            const uint32_t kb = st + (uint32_t)hf2 * 8192u;           // K rows hf2*64..
            const uint32_t vb = st + 16384u + (uint32_t)hf2 * 8192u;  // V^T half

            float sacc[2][8][4];
            #pragma unroll
            for (int m = 0; m < 2; m++)
                #pragma unroll
                for (int i = 0; i < 8; i++)
                    #pragma unroll
                    for (int k = 0; k < 4; k++) sacc[m][i][k] = 0.f;

            // S = Q K^T — K frags loaded ONCE, used by both m-frags
            #pragma unroll
            for (int ks = 0; ks < 4; ks++) {
                uint32_t qh[2][4];
                #pragma unroll
                for (int mf = 0; mf < 2; mf++) {
                    uint32_t relq = swz128((uint32_t)((wid*32 + mf*16 + (lane & 15)) * 128
                                           + (lane >> 4) * 16 + ks * 32));
                    ldm4(qh[mf], sb + relq);
                }
                uint32_t kf[8][2];
                #pragma unroll
                for (int nt = 0; nt < 4; nt++) {
                    uint32_t rel = swz128((uint32_t)((nt * 16 + (lane & 15)) * 128
                                          + (lane >> 4) * 16 + ks * 32));
                    uint32_t r[4];
                    ldm4(r, kb + rel);
                    kf[2*nt][0]=r[0]; kf[2*nt][1]=r[2]; kf[2*nt+1][0]=r[1]; kf[2*nt+1][1]=r[3];
                }
                #pragma unroll
                for (int mf = 0; mf < 2; mf++)
                    #pragma unroll
                    for (int nf = 0; nf < 8; nf++)
                        mma_f16(sacc[mf][nf], qh[mf], kf[nf]);
            }

            // P = ex2(s * 0.125*log2(e)) in packed fp16; l += P @ ones
            uint32_t pah[2][4][4];
            #pragma unroll
            for (int mf = 0; mf < 2; mf++) {
                #pragma unroll
                for (int kk = 0; kk < 4; kk++) {
                    pah[mf][kk][0] = ex2h2(pack2h(sacc[mf][2*kk][0]   * C8, sacc[mf][2*kk][1]   * C8));
                    pah[mf][kk][1] = ex2h2(pack2h(sacc[mf][2*kk][2]   * C8, sacc[mf][2*kk][3]   * C8));
                    pah[mf][kk][2] = ex2h2(pack2h(sacc[mf][2*kk+1][0] * C8, sacc[mf][2*kk+1][1] * C8));
                    pah[mf][kk][3] = ex2h2(pack2h(sacc[mf][2*kk+1][2] * C8, sacc[mf][2*kk+1][3] * C8));
                }
                #pragma unroll
                for (int ks = 0; ks < 4; ks++)
                    mma_f16(lacc[mf], pah[mf][ks], onesb);
            }

            // O += P V — V frags loaded ONCE, used by both m-frags
            #pragma unroll
            for (int ks = 0; ks < 4; ks++) {
                uint32_t vf[8][2];
                #pragma unroll
                for (int nt = 0; nt < 4; nt++) {
                    uint32_t rel = swz128((uint32_t)((nt * 16 + (lane & 15)) * 128
                                          + (lane >> 4) * 16 + ks * 32));
                    uint32_t r[4];
                    ldm4(r, vb + rel);
                    vf[2*nt][0]=r[0]; vf[2*nt][1]=r[2]; vf[2*nt+1][0]=r[1]; vf[2*nt+1][1]=r[3];
                }
                #pragma unroll
                for (int mf = 0; mf < 2; mf++)
                    #pragma unroll
                    for (int nf = 0; nf < 8; nf++)
                        mma_f16(oacc[mf][nf], pah[mf][ks], vf[nf]);
            }
        }
    }

    // epilogue: O/l per m-frag (lacc[mf][0]/[2] hold the two row sums)
    #pragma unroll
    for (int mf = 0; mf < 2; mf++) {
        const float inv0 = 64.f / lacc[mf][0], inv1 = 64.f / lacc[mf][2];
        const int n0 = q0 + wid * 32 + mf * 16 + (lane >> 2);
        #pragma unroll
        for (int nf = 0; nf < 8; nf++) {
            int d = nf * 8 + (lane & 3) * 2;
            int col = h * DH + d;
            uint32_t hv, lv;
            split2h(oacc[mf][nf][0] * inv0, oacc[mf][nf][1] * inv0, hv, lv);
            size_t o0 = ((size_t)b * SEQ + n0) * CD + col;
            *(uint32_t*)(g_Oh + o0) = hv; *(uint32_t*)(g_Ol + o0) = lv;
            split2h(oacc[mf][nf][2] * inv1, oacc[mf][nf][3] * inv1, hv, lv);
            size_t o1 = ((size_t)b * SEQ + n0 + 8) * CD + col;
            *(uint32_t*)(g_Oh + o1) = hv; *(uint32_t*)(g_Ol + o1) = lv;
        }
    }
}

// ---------------------------------------------------------------------------
extern "C" void kernel_launch(void* const* d_in, const int* in_sizes, int n_in,
                              void* d_out, int out_size) {
    const float* x   = (const float*)d_in[0];
    const float* ctx = (const float*)d_in[1];
    const float* Wq  = (const float*)d_in[2];
    const float* Wk  = (const float*)d_in[3];
    const float* Wv  = (const float*)d_in[4];
    const float* Wo  = (const float*)d_in[5];
    const float* bo  = (const float*)d_in[6];
    float* out = (float*)d_out;

    static int inited = 0;
    if (!inited) {
        cudaFuncSetAttribute(proj_mma, cudaFuncAttributeMaxDynamicSharedMemorySize, 2 * PJ_STG);
        cudaFuncSetAttribute(out_mma,  cudaFuncAttributeMaxDynamicSharedMemorySize, 2 * PJ_STG);
        cudaFuncSetAttribute(attn_mma, cudaFuncAttributeMaxDynamicSharedMemorySize, 98304);
        inited = 1;
    }

    cvt_act<<<2 * ROWS * CD / 4 / 256, 256>>>(x, ctx);
    cvt_w<<<4 * CD * CD / 256, 256>>>(Wq, Wk, Wv, Wo);
    proj_mma<<<dim3(4, 64, 3), 256, 2 * PJ_STG>>>();
    attn_mma<<<dim3(SEQ / 256, HH, BB), 256, 98304>>>();
    out_mma<<<dim3(4, 64), 256, 2 * PJ_STG>>>(bo, out);
}